// round 9
// baseline (speedup 1.0000x reference)
#include <cuda_runtime.h>
#include <cuda_fp16.h>
#include <math.h>
#include <stdint.h>

#define BB 4
#define SEQ 8192
#define DIM 256
#define NH 8
#define HD 32
#define INTERNAL 256
#define QKVO 1024
#define KK 512                      // split K (2 x 256)
#define SCALE_F 0.17677669529663687f
#define S_CONST 0.00464534038f

// ---------------- scratch ----------------
__device__ __align__(16) float g_qkvo[(size_t)BB * SEQ * QKVO];      // 128 MB
__device__ __align__(16) __half g_xs[(size_t)BB * SEQ * KK];         // 32 MB
__device__ __align__(16) __half g_ws[(size_t)QKVO * KK];             // 1 MB
__device__ __align__(16) __half g_tmph[(size_t)BB * SEQ * KK];       // 32 MB
__device__ __align__(16) __half g_wp[(size_t)DIM * KK];              // 256 KB
__device__ float g_kv[BB * NH * HD * HD];
__device__ float g_km[BB * NH * HD];
__device__ float g_vm[BB * NH * HD];

__device__ __forceinline__ float elu1(float x) { return x > 0.f ? x + 1.f : __expf(x); }

__device__ __forceinline__ uint32_t smem_u32(const void* p) {
    return (uint32_t)__cvta_generic_to_shared(p);
}
__device__ __forceinline__ void cpa16(uint32_t dst, const void* src) {
    asm volatile("cp.async.cg.shared.global [%0], [%1], 16;" :: "r"(dst), "l"(src));
}
__device__ __forceinline__ void cpa_commit() {
    asm volatile("cp.async.commit_group;" ::: "memory");
}
template <int N> __device__ __forceinline__ void cpa_wait() {
    asm volatile("cp.async.wait_group %0;" :: "n"(N) : "memory");
}
#define LDSM4(r, a) \
    asm volatile("ldmatrix.sync.aligned.m8n8.x4.shared.b16 {%0,%1,%2,%3}, [%4];" \
                 : "=r"((r)[0]), "=r"((r)[1]), "=r"((r)[2]), "=r"((r)[3]) : "r"(a))
#define MMA16816(d, a, b0, b1) \
    asm volatile("mma.sync.aligned.m16n8k16.row.col.f32.f16.f16.f32 " \
                 "{%0,%1,%2,%3},{%4,%5,%6,%7},{%8,%9},{%0,%1,%2,%3};" \
                 : "+f"((d)[0]), "+f"((d)[1]), "+f"((d)[2]), "+f"((d)[3]) \
                 : "r"((a)[0]), "r"((a)[1]), "r"((a)[2]), "r"((a)[3]), "r"(b0), "r"(b1))

// ---------------- GEMM config: 128x128 CTA, warp tile 32x64, 2 CTAs/SM ----------------
#define BM 128
#define BN 128
#define BK 64
#define NCH (KK / BK)               // 8
#define NSTG 3
#define TILEA (BM * 128)            // 16384 B
#define TILEB (BN * 128)            // 16384 B
#define STGB (TILEA + TILEB)        // 32768 B
#define GEMM_SMEM (NSTG * STGB)     // 98304 B

__device__ __forceinline__ void stage_tiles(uint32_t sb, const __half* Ab,
                                            const __half* Bb, int tid,
                                            int chunk, int buf) {
    const uint32_t ab = sb + buf * STGB;
    const uint32_t bbse = ab + TILEA;
    const __half* Ap = Ab + chunk * BK;
    const __half* Bp = Bb + chunk * BK;
#pragma unroll
    for (int i = 0; i < 4; i++) {
        int line = tid + i * 256;            // 0..1023
        int row = line >> 3, j = line & 7;
        uint32_t sw = row * 128 + ((j ^ (row & 7)) << 4);
        cpa16(ab + sw, Ap + (size_t)row * KK + j * 8);
    }
#pragma unroll
    for (int i = 0; i < 4; i++) {
        int line = tid + i * 256;
        int row = line >> 3, j = line & 7;
        uint32_t sw = row * 128 + ((j ^ (row & 7)) << 4);
        cpa16(bbse + sw, Bp + (size_t)row * KK + j * 8);
    }
    cpa_commit();
}

// C[M,Nn] = A'[M,512]h @ B'[Nn,512]h^T + bias (fp32 accum)
__global__ __launch_bounds__(256, 2)
void gemm_half(const __half* __restrict__ A, const __half* __restrict__ Bm,
               const float* __restrict__ bias, float* __restrict__ C, int Nn) {
    extern __shared__ char smem[];
    const uint32_t sb = smem_u32(smem);
    const int tid = threadIdx.x;
    const int wid = tid >> 5;
    const int lane = tid & 31;
    const int bm = blockIdx.y * BM;
    const int bn = blockIdx.x * BN;
    const int wm0 = (wid & 3) * 32;          // 4 warps in M
    const int wn0 = (wid >> 2) * 64;         // 2 warps in N

    const __half* Ab = A + (size_t)bm * KK;
    const __half* Bb = Bm + (size_t)bn * KK;

    float acc[2][8][4];
#pragma unroll
    for (int i = 0; i < 2; i++)
#pragma unroll
        for (int j = 0; j < 8; j++)
#pragma unroll
            for (int k = 0; k < 4; k++) acc[i][j][k] = 0.f;

    const int lrA = (lane & 7) + ((lane >> 3) & 1) * 8;
    const int lcA = ((lane >> 4) & 1) * 16;
    const int lrB = ((lane >> 4) & 1) * 8 + (lane & 7);
    const int lcB = ((lane >> 3) & 1) * 16;

    stage_tiles(sb, Ab, Bb, tid, 0, 0);
    stage_tiles(sb, Ab, Bb, tid, 1, 1);

#pragma unroll
    for (int c = 0; c < NCH; c++) {
        if (c + 2 < NCH) cpa_wait<1>(); else cpa_wait<0>();
        __syncthreads();
        if (c + 2 < NCH) stage_tiles(sb, Ab, Bb, tid, c + 2, (c + 2) % NSTG);
        const uint32_t ab = sb + (c % NSTG) * STGB;
        const uint32_t bbse = ab + TILEA;
#pragma unroll
        for (int ks = 0; ks < 4; ks++) {
            uint32_t afr[2][4], bfr[4][4];
#pragma unroll
            for (int mi = 0; mi < 2; mi++) {
                int r = wm0 + mi * 16 + lrA;
                uint32_t cc = (uint32_t)(ks * 32 + lcA);
                LDSM4(afr[mi], ab + r * 128 + (cc ^ ((r & 7) << 4)));
            }
#pragma unroll
            for (int bi = 0; bi < 4; bi++) {
                int r = wn0 + bi * 16 + lrB;
                uint32_t cc = (uint32_t)(ks * 32 + lcB);
                LDSM4(bfr[bi], bbse + r * 128 + (cc ^ ((r & 7) << 4)));
            }
#pragma unroll
            for (int mi = 0; mi < 2; mi++)
#pragma unroll
                for (int nj = 0; nj < 8; nj++)
                    MMA16816(acc[mi][nj], afr[mi],
                             bfr[nj >> 1][(nj & 1) * 2], bfr[nj >> 1][(nj & 1) * 2 + 1]);
        }
    }

    const int g = lane >> 2, t4 = lane & 3;
#pragma unroll
    for (int mi = 0; mi < 2; mi++) {
#pragma unroll
        for (int nj = 0; nj < 8; nj++) {
            const int col = bn + wn0 + nj * 8 + t4 * 2;
            const float2 bv = *(const float2*)(bias + col);
            const int row0 = bm + wm0 + mi * 16 + g;
            float2 o0 = {acc[mi][nj][0] + bv.x, acc[mi][nj][1] + bv.y};
            float2 o1 = {acc[mi][nj][2] + bv.x, acc[mi][nj][3] + bv.y};
            *(float2*)(C + (size_t)row0 * Nn + col) = o0;
            *(float2*)(C + (size_t)(row0 + 8) * Nn + col) = o1;
        }
    }
}

// ---------------- fused prep: all splits + accumulator zeroing, one launch ----------------
#define TX (BB * SEQ * DIM)         // 8388608
#define TW (QKVO * DIM)             // 262144
#define TP (DIM * DIM)              // 65536
#define NKV (BB * NH * HD * HD)     // 32768
#define NKM (BB * NH * HD)          // 1024
#define TTOT (TX + TW + TP + NKV + 2 * NKM)

__global__ void prep_kernel(const float* __restrict__ x,
                            const float* __restrict__ W_qkvo,
                            const float* __restrict__ W_proj) {
    int i = blockIdx.x * 256 + threadIdx.x;
    if (i >= TTOT) return;
    if (i < TX) {
        int row = i >> 8, c = i & 255;
        float v = x[i];
        __half hi = __float2half_rn(v);
        __half lo = __float2half_rn(v - __half2float(hi));
        size_t base = (size_t)row * KK + c;
        g_xs[base] = hi;
        g_xs[base + 256] = lo;               // A operand: [hi | lo]
    } else if (i < TX + TW) {
        int k = i - TX;
        int row = k >> 8, c = k & 255;
        float v = W_qkvo[k];
        __half hi = __float2half_rn(v);
        size_t base = (size_t)row * KK + c;
        g_ws[base] = hi;
        g_ws[base + 256] = hi;               // B operand: [hi | hi]
    } else if (i < TX + TW + TP) {
        int k = i - TX - TW;
        int row = k >> 8, c = k & 255;
        float v = W_proj[k];
        __half hi = __float2half_rn(v);
        size_t base = (size_t)row * KK + c;
        g_wp[base] = hi;
        g_wp[base + 256] = hi;
    } else {
        int k = i - TX - TW - TP;
        if (k < NKV) g_kv[k] = 0.f;
        else if (k < NKV + NKM) g_km[k - NKV] = 0.f;
        else g_vm[k - NKV - NKM] = 0.f;
    }
}

// ---------------- per-(b,h) state reduction: double-buffered, 1 sync / 8 tokens ----------
#define CHUNK 512
#define NIT (CHUNK / 8)
__global__ __launch_bounds__(256)
void reduce_kernel(const float* __restrict__ sinp, const float* __restrict__ cosp) {
    const int bh = blockIdx.x;
    const int chunk = blockIdx.y;
    const int b = bh / NH, h = bh % NH;
    const int tid = threadIdx.x;
    const int j = tid >> 5;                  // token sub 0..7
    const int d = tid & 31;
    const int dbase = j * 4;
    __shared__ float s_ks[2][8][32];
    __shared__ float s_vs[2][8][32];
    float acc[4] = {0.f, 0.f, 0.f, 0.f};
    float ksum = 0.f, vsum = 0.f;
    const int n0 = chunk * CHUNK;
    const float sgn = (d & 1) ? 1.f : -1.f;
    const size_t kcol = INTERNAL + h * HD;
    const size_t vcol = 2 * INTERNAL + h * HD;

    {
        const int n = n0 + j;
        const size_t row = ((size_t)b * SEQ + n) * QKVO;
        const float kh  = elu1(g_qkvo[row + kcol + d]);
        const float khp = elu1(g_qkvo[row + kcol + (d ^ 1)]);
        const float vv  = g_qkvo[row + vcol + d];
        const float sn = sinp[n * HD + d];
        const float cs = cosp[n * HD + d];
        s_ks[0][j][d] = (kh * cs + sgn * khp * sn) * S_CONST;
        s_vs[0][j][d] = vv * S_CONST;
        ksum += kh;
        vsum += vv;
    }
    __syncthreads();

    for (int it = 0; it < NIT; it++) {
        const int bsel = it & 1;
        float nk = 0.f, nkp = 0.f, nv = 0.f, nsn = 0.f, ncs = 0.f;
        const bool more = (it + 1 < NIT);
        if (more) {
            const int n = n0 + (it + 1) * 8 + j;
            const size_t row = ((size_t)b * SEQ + n) * QKVO;
            nk  = g_qkvo[row + kcol + d];
            nkp = g_qkvo[row + kcol + (d ^ 1)];
            nv  = g_qkvo[row + vcol + d];
            nsn = sinp[n * HD + d];
            ncs = cosp[n * HD + d];
        }
#pragma unroll
        for (int jj = 0; jj < 8; jj++) {
            const float vv = s_vs[bsel][jj][d];
#pragma unroll
            for (int dd = 0; dd < 4; dd++)
                acc[dd] += s_ks[bsel][jj][dbase + dd] * vv;
        }
        if (more) {
            const float kh = elu1(nk);
            const float khp = elu1(nkp);
            s_ks[bsel ^ 1][j][d] = (kh * ncs + sgn * khp * nsn) * S_CONST;
            s_vs[bsel ^ 1][j][d] = nv * S_CONST;
            ksum += kh;
            vsum += nv;
        }
        __syncthreads();
    }
#pragma unroll
    for (int dd = 0; dd < 4; dd++)
        atomicAdd(&g_kv[(bh * HD + dbase + dd) * HD + d], acc[dd]);
    atomicAdd(&g_km[bh * HD + d], ksum);
    atomicAdd(&g_vm[bh * HD + d], vsum);
}

// ---------------- attn epilogue: thread-per-(token,head), zero shuffles ----------------
#define ATB 256
__global__ __launch_bounds__(256)
void attn_kernel(const float* __restrict__ sinp, const float* __restrict__ cosp,
                 const float* __restrict__ W_lepe, const float* __restrict__ b_lepe) {
    const int b = blockIdx.y;
    const int h = blockIdx.z;
    const int n = blockIdx.x * ATB + threadIdx.x;
    const int bh = b * NH + h;
    __shared__ __align__(16) float s_kv[HD][HD];
    __shared__ float s_km[HD], s_vm[HD], s_w0[HD], s_w1[HD], s_w2[HD], s_bl[HD];

    for (int i = threadIdx.x; i < HD * HD; i += 256)
        ((float*)s_kv)[i] = g_kv[bh * HD * HD + i];
    if (threadIdx.x < HD) {
        const int c = h * HD + threadIdx.x;
        const float invN = 1.f / (float)SEQ;
        s_km[threadIdx.x] = g_km[bh * HD + threadIdx.x] * invN;
        s_vm[threadIdx.x] = g_vm[bh * HD + threadIdx.x] * invN;
        s_w0[threadIdx.x] = W_lepe[c * 3 + 0];
        s_w1[threadIdx.x] = W_lepe[c * 3 + 1];
        s_w2[threadIdx.x] = W_lepe[c * 3 + 2];
        s_bl[threadIdx.x] = b_lepe[c];
    }
    __syncthreads();

    const size_t row = ((size_t)b * SEQ + n) * QKVO;
    const int cb = h * HD;

    float qh[HD];
#pragma unroll
    for (int d4 = 0; d4 < 8; d4++) {
        float4 v = *(const float4*)(g_qkvo + row + cb + d4 * 4);
        qh[d4 * 4 + 0] = elu1(v.x);
        qh[d4 * 4 + 1] = elu1(v.y);
        qh[d4 * 4 + 2] = elu1(v.z);
        qh[d4 * 4 + 3] = elu1(v.w);
    }
    float z = 0.f;
#pragma unroll
    for (int d = 0; d < HD; d++) z += qh[d] * s_km[d];
    z *= SCALE_F;

#pragma unroll
    for (int d4 = 0; d4 < 8; d4++) {
        float4 sn = *(const float4*)(sinp + (size_t)n * HD + d4 * 4);
        float4 cs = *(const float4*)(cosp + (size_t)n * HD + d4 * 4);
        const float a0 = qh[d4 * 4 + 0], a1 = qh[d4 * 4 + 1];
        const float a2 = qh[d4 * 4 + 2], a3 = qh[d4 * 4 + 3];
        qh[d4 * 4 + 0] = a0 * cs.x - a1 * sn.x;
        qh[d4 * 4 + 1] = a1 * cs.y + a0 * sn.y;
        qh[d4 * 4 + 2] = a2 * cs.z - a3 * sn.z;
        qh[d4 * 4 + 3] = a3 * cs.w + a2 * sn.w;
    }

    float acc[HD];
#pragma unroll
    for (int e = 0; e < HD; e++) acc[e] = 0.f;
#pragma unroll
    for (int d = 0; d < HD; d++) {
        const float qd = qh[d];
        const float4* kvr = (const float4*)s_kv[d];
#pragma unroll
        for (int e4 = 0; e4 < 8; e4++) {
            float4 kv4 = kvr[e4];
            acc[e4 * 4 + 0] += qd * kv4.x;
            acc[e4 * 4 + 1] += qd * kv4.y;
            acc[e4 * 4 + 2] += qd * kv4.z;
            acc[e4 * 4 + 3] += qd * kv4.w;
        }
    }

    const float zf = 1.f + 1.f / (z + 1e-6f);
    const bool hp = (n > 0), hn = (n < SEQ - 1);
    const float* vrow = g_qkvo + row + 2 * INTERNAL + cb;
    const float* orow = g_qkvo + row + 3 * INTERNAL + cb;
    __half* outp = g_tmph + ((size_t)b * SEQ + n) * KK + cb;

#pragma unroll
    for (int e4 = 0; e4 < 8; e4++) {
        const float4 v0 = *(const float4*)(vrow + e4 * 4);
        const float4 vp = hp ? *(const float4*)(vrow - QKVO + e4 * 4) : make_float4(0, 0, 0, 0);
        const float4 vn = hn ? *(const float4*)(vrow + QKVO + e4 * 4) : make_float4(0, 0, 0, 0);
        const float4 og = *(const float4*)(orow + e4 * 4);
        const int e = e4 * 4;
        float r0 = (acc[e + 0] * zf - z * s_vm[e + 0]
                    + vp.x * s_w0[e + 0] + v0.x * s_w1[e + 0] + vn.x * s_w2[e + 0] + s_bl[e + 0]) * og.x;
        float r1 = (acc[e + 1] * zf - z * s_vm[e + 1]
                    + vp.y * s_w0[e + 1] + v0.y * s_w1[e + 1] + vn.y * s_w2[e + 1] + s_bl[e + 1]) * og.y;
        float r2 = (acc[e + 2] * zf - z * s_vm[e + 2]
                    + vp.z * s_w0[e + 2] + v0.z * s_w1[e + 2] + vn.z * s_w2[e + 2] + s_bl[e + 2]) * og.z;
        float r3 = (acc[e + 3] * zf - z * s_vm[e + 3]
                    + vp.w * s_w0[e + 3] + v0.w * s_w1[e + 3] + vn.w * s_w2[e + 3] + s_bl[e + 3]) * og.w;
        __half h0 = __float2half_rn(r0), h1 = __float2half_rn(r1);
        __half h2 = __float2half_rn(r2), h3 = __float2half_rn(r3);
        __half l0 = __float2half_rn(r0 - __half2float(h0));
        __half l1 = __float2half_rn(r1 - __half2float(h1));
        __half l2 = __float2half_rn(r2 - __half2float(h2));
        __half l3 = __float2half_rn(r3 - __half2float(h3));
        uint2 hw, lw;
        hw.x = ((uint32_t)__half_as_ushort(h1) << 16) | __half_as_ushort(h0);
        hw.y = ((uint32_t)__half_as_ushort(h3) << 16) | __half_as_ushort(h2);
        lw.x = ((uint32_t)__half_as_ushort(l1) << 16) | __half_as_ushort(l0);
        lw.y = ((uint32_t)__half_as_ushort(l3) << 16) | __half_as_ushort(l2);
        *(uint2*)(outp + e) = hw;
        *(uint2*)(outp + 256 + e) = lw;
    }
}

// ---------------- launch ----------------
extern "C" void kernel_launch(void* const* d_in, const int* in_sizes, int n_in,
                              void* d_out, int out_size) {
    const float* x      = (const float*)d_in[0];
    const float* sinp   = (const float*)d_in[1];
    const float* cosp   = (const float*)d_in[2];
    const float* W_qkvo = (const float*)d_in[3];
    const float* b_qkvo = (const float*)d_in[4];
    const float* W_lepe = (const float*)d_in[5];
    const float* b_lepe = (const float*)d_in[6];
    const float* W_proj = (const float*)d_in[7];
    const float* b_proj = (const float*)d_in[8];
    float* out = (float*)d_out;

    __half *xs_p, *ws_p, *tmph_p, *wp_p;
    float* qkvo_p;
    cudaGetSymbolAddress((void**)&qkvo_p, g_qkvo);
    cudaGetSymbolAddress((void**)&xs_p, g_xs);
    cudaGetSymbolAddress((void**)&ws_p, g_ws);
    cudaGetSymbolAddress((void**)&tmph_p, g_tmph);
    cudaGetSymbolAddress((void**)&wp_p, g_wp);

    cudaFuncSetAttribute(gemm_half, cudaFuncAttributeMaxDynamicSharedMemorySize, GEMM_SMEM);

    const int M = BB * SEQ;  // 32768

    // 0) fused splits + zeroing, one launch
    prep_kernel<<<(TTOT + 255) / 256, 256>>>(x, W_qkvo, W_proj);

    // 1) qkvo = x @ W_qkvo^T + b  (HMMA, K=512 split)
    {
        dim3 grid(QKVO / BN, M / BM);
        gemm_half<<<grid, 256, GEMM_SMEM>>>(xs_p, ws_p, b_qkvo, qkvo_p, QKVO);
    }
    // 2) state reduction
    {
        dim3 grid(BB * NH, SEQ / CHUNK);
        reduce_kernel<<<grid, 256>>>(sinp, cosp);
    }
    // 3) attention epilogue
    {
        dim3 grid(SEQ / ATB, BB, NH);
        attn_kernel<<<grid, 256>>>(sinp, cosp, W_lepe, b_lepe);
    }
    // 4) out = tmp @ W_proj^T + b_proj  (HMMA)
    {
        dim3 grid(DIM / BN, M / BM);
        gemm_half<<<grid, 256, GEMM_SMEM>>>(tmph_p, wp_p, b_proj, out, DIM);
    }
}

// round 10
// speedup vs baseline: 1.4023x; 1.4023x over previous
#include <cuda_runtime.h>
#include <cuda_fp16.h>
#include <math.h>
#include <stdint.h>

#define BB 4
#define SEQ 8192
#define DIM 256
#define NH 8
#define HD 32
#define INTERNAL 256
#define QKVO 1024
#define KK 512                      // split K (2 x 256)
#define SCALE_F 0.17677669529663687f
#define S_CONST 0.00464534038f

// ---------------- scratch ----------------
__device__ __align__(16) float g_qkvo[(size_t)BB * SEQ * QKVO];      // 128 MB
__device__ __align__(16) __half g_xs[(size_t)BB * SEQ * KK];         // 32 MB
__device__ __align__(16) __half g_ws[(size_t)QKVO * KK];             // 1 MB
__device__ __align__(16) __half g_tmph[(size_t)BB * SEQ * KK];       // 32 MB
__device__ __align__(16) __half g_wp[(size_t)DIM * KK];              // 256 KB
__device__ float g_kv[BB * NH * HD * HD];
__device__ float g_km[BB * NH * HD];
__device__ float g_vm[BB * NH * HD];

__device__ __forceinline__ float elu1(float x) { return x > 0.f ? x + 1.f : __expf(x); }

__device__ __forceinline__ uint32_t smem_u32(const void* p) {
    return (uint32_t)__cvta_generic_to_shared(p);
}
__device__ __forceinline__ void cpa16(uint32_t dst, const void* src) {
    asm volatile("cp.async.cg.shared.global [%0], [%1], 16;" :: "r"(dst), "l"(src));
}
__device__ __forceinline__ void cpa_commit() {
    asm volatile("cp.async.commit_group;" ::: "memory");
}
template <int N> __device__ __forceinline__ void cpa_wait() {
    asm volatile("cp.async.wait_group %0;" :: "n"(N) : "memory");
}
#define LDSM4(r, a) \
    asm volatile("ldmatrix.sync.aligned.m8n8.x4.shared.b16 {%0,%1,%2,%3}, [%4];" \
                 : "=r"((r)[0]), "=r"((r)[1]), "=r"((r)[2]), "=r"((r)[3]) : "r"(a))
#define MMA16816(d, a, b0, b1) \
    asm volatile("mma.sync.aligned.m16n8k16.row.col.f32.f16.f16.f32 " \
                 "{%0,%1,%2,%3},{%4,%5,%6,%7},{%8,%9},{%0,%1,%2,%3};" \
                 : "+f"((d)[0]), "+f"((d)[1]), "+f"((d)[2]), "+f"((d)[3]) \
                 : "r"((a)[0]), "r"((a)[1]), "r"((a)[2]), "r"((a)[3]), "r"(b0), "r"(b1))

// ---------------- GEMM config: 128x128 CTA, warp tile 32x64, 2 CTAs/SM ----------------
#define BM 128
#define BN 128
#define BK 64
#define NCH (KK / BK)               // 8
#define NSTG 3
#define TILEA (BM * 128)            // 16384 B
#define TILEB (BN * 128)            // 16384 B
#define STGB (TILEA + TILEB)        // 32768 B
#define GEMM_SMEM (NSTG * STGB)     // 98304 B

__device__ __forceinline__ void stage_tiles(uint32_t sb, const __half* Ab,
                                            const __half* Bb, int tid,
                                            int chunk, int buf) {
    const uint32_t ab = sb + buf * STGB;
    const uint32_t bbse = ab + TILEA;
    const __half* Ap = Ab + chunk * BK;
    const __half* Bp = Bb + chunk * BK;
#pragma unroll
    for (int i = 0; i < 4; i++) {
        int line = tid + i * 256;            // 0..1023
        int row = line >> 3, j = line & 7;
        uint32_t sw = row * 128 + ((j ^ (row & 7)) << 4);
        cpa16(ab + sw, Ap + (size_t)row * KK + j * 8);
    }
#pragma unroll
    for (int i = 0; i < 4; i++) {
        int line = tid + i * 256;
        int row = line >> 3, j = line & 7;
        uint32_t sw = row * 128 + ((j ^ (row & 7)) << 4);
        cpa16(bbse + sw, Bp + (size_t)row * KK + j * 8);
    }
    cpa_commit();
}

// C[M,Nn] = A'[M,512]h @ B'[Nn,512]h^T + bias (fp32 accum)
__global__ __launch_bounds__(256, 2)
void gemm_half(const __half* __restrict__ A, const __half* __restrict__ Bm,
               const float* __restrict__ bias, float* __restrict__ C, int Nn) {
    extern __shared__ char smem[];
    const uint32_t sb = smem_u32(smem);
    const int tid = threadIdx.x;
    const int wid = tid >> 5;
    const int lane = tid & 31;
    const int bm = blockIdx.y * BM;
    const int bn = blockIdx.x * BN;
    const int wm0 = (wid & 3) * 32;          // 4 warps in M
    const int wn0 = (wid >> 2) * 64;         // 2 warps in N

    const __half* Ab = A + (size_t)bm * KK;
    const __half* Bb = Bm + (size_t)bn * KK;

    float acc[2][8][4];
#pragma unroll
    for (int i = 0; i < 2; i++)
#pragma unroll
        for (int j = 0; j < 8; j++)
#pragma unroll
            for (int k = 0; k < 4; k++) acc[i][j][k] = 0.f;

    const int lrA = (lane & 7) + ((lane >> 3) & 1) * 8;
    const int lcA = ((lane >> 4) & 1) * 16;
    const int lrB = ((lane >> 4) & 1) * 8 + (lane & 7);
    const int lcB = ((lane >> 3) & 1) * 16;

    stage_tiles(sb, Ab, Bb, tid, 0, 0);
    stage_tiles(sb, Ab, Bb, tid, 1, 1);

    for (int c = 0; c < NCH; c++) {
        if (c + 2 < NCH) cpa_wait<1>(); else cpa_wait<0>();
        __syncthreads();
        if (c + 2 < NCH) stage_tiles(sb, Ab, Bb, tid, c + 2, (c + 2) % NSTG);
        const uint32_t ab = sb + (c % NSTG) * STGB;
        const uint32_t bbse = ab + TILEA;
#pragma unroll
        for (int ks = 0; ks < 4; ks++) {
            uint32_t afr[2][4], bfr[4][4];
#pragma unroll
            for (int mi = 0; mi < 2; mi++) {
                int r = wm0 + mi * 16 + lrA;
                uint32_t cc = (uint32_t)(ks * 32 + lcA);
                LDSM4(afr[mi], ab + r * 128 + (cc ^ ((r & 7) << 4)));
            }
#pragma unroll
            for (int bi = 0; bi < 4; bi++) {
                int r = wn0 + bi * 16 + lrB;
                uint32_t cc = (uint32_t)(ks * 32 + lcB);
                LDSM4(bfr[bi], bbse + r * 128 + (cc ^ ((r & 7) << 4)));
            }
#pragma unroll
            for (int mi = 0; mi < 2; mi++)
#pragma unroll
                for (int nj = 0; nj < 8; nj++)
                    MMA16816(acc[mi][nj], afr[mi],
                             bfr[nj >> 1][(nj & 1) * 2], bfr[nj >> 1][(nj & 1) * 2 + 1]);
        }
    }

    const int g = lane >> 2, t4 = lane & 3;
#pragma unroll
    for (int mi = 0; mi < 2; mi++) {
#pragma unroll
        for (int nj = 0; nj < 8; nj++) {
            const int col = bn + wn0 + nj * 8 + t4 * 2;
            const float2 bv = *(const float2*)(bias + col);
            const int row0 = bm + wm0 + mi * 16 + g;
            float2 o0 = {acc[mi][nj][0] + bv.x, acc[mi][nj][1] + bv.y};
            float2 o1 = {acc[mi][nj][2] + bv.x, acc[mi][nj][3] + bv.y};
            *(float2*)(C + (size_t)row0 * Nn + col) = o0;
            *(float2*)(C + (size_t)(row0 + 8) * Nn + col) = o1;
        }
    }
}

// ---------------- fused prep: all splits + accumulator zeroing, one launch ----------------
#define TX (BB * SEQ * DIM)         // 8388608
#define TW (QKVO * DIM)             // 262144
#define TP (DIM * DIM)              // 65536
#define NKV (BB * NH * HD * HD)     // 32768
#define NKM (BB * NH * HD)          // 1024
#define TTOT (TX + TW + TP + NKV + 2 * NKM)

__global__ void prep_kernel(const float* __restrict__ x,
                            const float* __restrict__ W_qkvo,
                            const float* __restrict__ W_proj) {
    int i = blockIdx.x * 256 + threadIdx.x;
    if (i >= TTOT) return;
    if (i < TX) {
        int row = i >> 8, c = i & 255;
        float v = x[i];
        __half hi = __float2half_rn(v);
        __half lo = __float2half_rn(v - __half2float(hi));
        size_t base = (size_t)row * KK + c;
        g_xs[base] = hi;
        g_xs[base + 256] = lo;               // A operand: [hi | lo]
    } else if (i < TX + TW) {
        int k = i - TX;
        int row = k >> 8, c = k & 255;
        float v = W_qkvo[k];
        __half hi = __float2half_rn(v);
        size_t base = (size_t)row * KK + c;
        g_ws[base] = hi;
        g_ws[base + 256] = hi;               // B operand: [hi | hi]
    } else if (i < TX + TW + TP) {
        int k = i - TX - TW;
        int row = k >> 8, c = k & 255;
        float v = W_proj[k];
        __half hi = __float2half_rn(v);
        size_t base = (size_t)row * KK + c;
        g_wp[base] = hi;
        g_wp[base + 256] = hi;
    } else {
        int k = i - TX - TW - TP;
        if (k < NKV) g_kv[k] = 0.f;
        else if (k < NKV + NKM) g_km[k - NKV] = 0.f;
        else g_vm[k - NKV - NKM] = 0.f;
    }
}

// ---------------- per-(b,h) state reduction: double-buffered, 1 sync / 8 tokens ----------
#define CHUNK 512
#define NIT (CHUNK / 8)
__global__ __launch_bounds__(256)
void reduce_kernel(const float* __restrict__ sinp, const float* __restrict__ cosp) {
    const int bh = blockIdx.x;
    const int chunk = blockIdx.y;
    const int b = bh / NH, h = bh % NH;
    const int tid = threadIdx.x;
    const int j = tid >> 5;                  // token sub 0..7
    const int d = tid & 31;
    const int dbase = j * 4;
    __shared__ float s_ks[2][8][32];
    __shared__ float s_vs[2][8][32];
    float acc[4] = {0.f, 0.f, 0.f, 0.f};
    float ksum = 0.f, vsum = 0.f;
    const int n0 = chunk * CHUNK;
    const float sgn = (d & 1) ? 1.f : -1.f;
    const size_t kcol = INTERNAL + h * HD;
    const size_t vcol = 2 * INTERNAL + h * HD;

    {
        const int n = n0 + j;
        const size_t row = ((size_t)b * SEQ + n) * QKVO;
        const float kh  = elu1(g_qkvo[row + kcol + d]);
        const float khp = elu1(g_qkvo[row + kcol + (d ^ 1)]);
        const float vv  = g_qkvo[row + vcol + d];
        const float sn = sinp[n * HD + d];
        const float cs = cosp[n * HD + d];
        s_ks[0][j][d] = (kh * cs + sgn * khp * sn) * S_CONST;
        s_vs[0][j][d] = vv * S_CONST;
        ksum += kh;
        vsum += vv;
    }
    __syncthreads();

    for (int it = 0; it < NIT; it++) {
        const int bsel = it & 1;
        float nk = 0.f, nkp = 0.f, nv = 0.f, nsn = 0.f, ncs = 0.f;
        const bool more = (it + 1 < NIT);
        if (more) {
            const int n = n0 + (it + 1) * 8 + j;
            const size_t row = ((size_t)b * SEQ + n) * QKVO;
            nk  = g_qkvo[row + kcol + d];
            nkp = g_qkvo[row + kcol + (d ^ 1)];
            nv  = g_qkvo[row + vcol + d];
            nsn = sinp[n * HD + d];
            ncs = cosp[n * HD + d];
        }
#pragma unroll
        for (int jj = 0; jj < 8; jj++) {
            const float vv = s_vs[bsel][jj][d];
#pragma unroll
            for (int dd = 0; dd < 4; dd++)
                acc[dd] += s_ks[bsel][jj][dbase + dd] * vv;
        }
        if (more) {
            const float kh = elu1(nk);
            const float khp = elu1(nkp);
            s_ks[bsel ^ 1][j][d] = (kh * ncs + sgn * khp * nsn) * S_CONST;
            s_vs[bsel ^ 1][j][d] = nv * S_CONST;
            ksum += kh;
            vsum += nv;
        }
        __syncthreads();
    }
#pragma unroll
    for (int dd = 0; dd < 4; dd++)
        atomicAdd(&g_kv[(bh * HD + dbase + dd) * HD + d], acc[dd]);
    atomicAdd(&g_km[bh * HD + d], ksum);
    atomicAdd(&g_vm[bh * HD + d], vsum);
}

// ---------------- attn epilogue: HMMA matvec (128 tokens/block, 1 thread/token) --------
#define ATB 128
// swizzled byte offset for half index `colh` in a 128B row
__device__ __forceinline__ uint32_t swzh(int row, int colh) {
    int byt = colh * 2;
    return (uint32_t)(row * 128 + ((((byt >> 4) ^ (row & 7))) << 4) + (byt & 15));
}

__global__ __launch_bounds__(128)
void attn_kernel(const float* __restrict__ sinp, const float* __restrict__ cosp,
                 const float* __restrict__ W_lepe, const float* __restrict__ b_lepe) {
    const int b = blockIdx.y;
    const int h = blockIdx.z;
    const int bh = b * NH + h;
    const int tid = threadIdx.x;             // token within tile
    const int n = blockIdx.x * ATB + tid;
    const int wid = tid >> 5;
    const int lane = tid & 31;

    __shared__ __align__(16) char sA[ATB * 128];   // qs hi|lo, K=64 halves, swizzled
    __shared__ __align__(16) char sB[HD * 128];    // kv^T hi (dup), swizzled
    __shared__ float s_out[ATB * 36];              // acc tile, pitch 36 floats
    __shared__ float s_z[ATB];
    __shared__ float s_km[HD], s_vm[HD], s_w0[HD], s_w1[HD], s_w2[HD], s_bl[HD];

    // stage B (kv transposed, fp16, duplicated across K halves) + per-head constants
    {
        const int e = tid & 31, dg = tid >> 5;     // 4 groups x 8 d's
#pragma unroll
        for (int k = 0; k < 8; k++) {
            const int d = dg * 8 + k;
            const float kvv = g_kv[bh * HD * HD + d * HD + e];
            const __half hv = __float2half_rn(kvv);
            *(__half*)(sB + swzh(e, d)) = hv;
            *(__half*)(sB + swzh(e, 32 + d)) = hv;
        }
    }
    if (tid < HD) {
        const int c = h * HD + tid;
        const float invN = 1.f / (float)SEQ;
        s_km[tid] = g_km[bh * HD + tid] * invN;
        s_vm[tid] = g_vm[bh * HD + tid] * invN;
        s_w0[tid] = W_lepe[c * 3 + 0];
        s_w1[tid] = W_lepe[c * 3 + 1];
        s_w2[tid] = W_lepe[c * 3 + 2];
        s_bl[tid] = b_lepe[c];
    }
    __syncthreads();

    const size_t row = ((size_t)b * SEQ + n) * QKVO;
    const int cb = h * HD;

    // phase 1: elu, z, theta-shift; write qs hi|lo into sA
    {
        float qh[HD];
#pragma unroll
        for (int d4 = 0; d4 < 8; d4++) {
            float4 v = *(const float4*)(g_qkvo + row + cb + d4 * 4);
            qh[d4 * 4 + 0] = elu1(v.x);
            qh[d4 * 4 + 1] = elu1(v.y);
            qh[d4 * 4 + 2] = elu1(v.z);
            qh[d4 * 4 + 3] = elu1(v.w);
        }
        float z = 0.f;
#pragma unroll
        for (int d = 0; d < HD; d++) z += qh[d] * s_km[d];
        s_z[tid] = z * SCALE_F;

#pragma unroll
        for (int d4 = 0; d4 < 8; d4++) {
            float4 sn = *(const float4*)(sinp + (size_t)n * HD + d4 * 4);
            float4 cs = *(const float4*)(cosp + (size_t)n * HD + d4 * 4);
            const float a0 = qh[d4 * 4 + 0], a1 = qh[d4 * 4 + 1];
            const float a2 = qh[d4 * 4 + 2], a3 = qh[d4 * 4 + 3];
            qh[d4 * 4 + 0] = a0 * cs.x - a1 * sn.x;
            qh[d4 * 4 + 1] = a1 * cs.y + a0 * sn.y;
            qh[d4 * 4 + 2] = a2 * cs.z - a3 * sn.z;
            qh[d4 * 4 + 3] = a3 * cs.w + a2 * sn.w;
        }
        // chunks 0..3: hi(qs[0..31]); chunks 4..7: lo(qs[0..31])
#pragma unroll
        for (int j = 0; j < 8; j++) {
            __half hbuf[8];
#pragma unroll
            for (int u = 0; u < 8; u++) {
                const int k = j * 8 + u;
                const float q = qh[(k & 31)];
                const __half hi = __float2half_rn(q);
                hbuf[u] = (k < 32) ? hi : __float2half_rn(q - __half2float(hi));
            }
            *(uint4*)(sA + tid * 128 + ((j ^ (tid & 7)) << 4)) = *(uint4*)hbuf;
        }
    }
    __syncthreads();

    // phase 2: HMMA  [128 x 64] @ [32 x 64]^T -> s_out[128 x 32]
    {
        const uint32_t au = smem_u32(sA);
        const uint32_t bu = smem_u32(sB);
        const int wm0 = wid * 32;
        const int lrA = (lane & 7) + ((lane >> 3) & 1) * 8;
        const int lcA = ((lane >> 4) & 1) * 16;
        const int lrB = ((lane >> 4) & 1) * 8 + (lane & 7);
        const int lcB = ((lane >> 3) & 1) * 16;
        float acc[2][4][4];
#pragma unroll
        for (int i = 0; i < 2; i++)
#pragma unroll
            for (int j = 0; j < 4; j++)
#pragma unroll
                for (int k = 0; k < 4; k++) acc[i][j][k] = 0.f;
#pragma unroll
        for (int ks = 0; ks < 4; ks++) {
            uint32_t afr[2][4], bfr[2][4];
#pragma unroll
            for (int mi = 0; mi < 2; mi++) {
                const int r = wm0 + mi * 16 + lrA;
                const uint32_t cc = (uint32_t)(ks * 32 + lcA);
                LDSM4(afr[mi], au + r * 128 + (cc ^ ((r & 7) << 4)));
            }
#pragma unroll
            for (int bi = 0; bi < 2; bi++) {
                const int r = bi * 16 + lrB;
                const uint32_t cc = (uint32_t)(ks * 32 + lcB);
                LDSM4(bfr[bi], bu + r * 128 + (cc ^ ((r & 7) << 4)));
            }
#pragma unroll
            for (int mi = 0; mi < 2; mi++)
#pragma unroll
                for (int nj = 0; nj < 4; nj++)
                    MMA16816(acc[mi][nj], afr[mi],
                             bfr[nj >> 1][(nj & 1) * 2], bfr[nj >> 1][(nj & 1) * 2 + 1]);
        }
        const int g = lane >> 2, t4 = lane & 3;
#pragma unroll
        for (int mi = 0; mi < 2; mi++) {
#pragma unroll
            for (int nj = 0; nj < 4; nj++) {
                const int col = nj * 8 + t4 * 2;
                const int row0 = wm0 + mi * 16 + g;
                *(float2*)(s_out + row0 * 36 + col) = make_float2(acc[mi][nj][0], acc[mi][nj][1]);
                *(float2*)(s_out + (row0 + 8) * 36 + col) = make_float2(acc[mi][nj][2], acc[mi][nj][3]);
            }
        }
    }
    __syncthreads();

    // phase 3: per-token MALA correction + lepe + o-gate + hi/lo store
    const float z = s_z[tid];
    const float zf = 1.f + 1.f / (z + 1e-6f);
    const bool hp = (n > 0), hn = (n < SEQ - 1);
    const float* vrow = g_qkvo + row + 2 * INTERNAL + cb;
    const float* orow = g_qkvo + row + 3 * INTERNAL + cb;
    __half* outp = g_tmph + ((size_t)b * SEQ + n) * KK + cb;

#pragma unroll
    for (int e4 = 0; e4 < 8; e4++) {
        const float4 av = *(const float4*)(s_out + tid * 36 + e4 * 4);
        const float4 v0 = *(const float4*)(vrow + e4 * 4);
        const float4 vp = hp ? *(const float4*)(vrow - QKVO + e4 * 4) : make_float4(0, 0, 0, 0);
        const float4 vn = hn ? *(const float4*)(vrow + QKVO + e4 * 4) : make_float4(0, 0, 0, 0);
        const float4 og = *(const float4*)(orow + e4 * 4);
        const int e = e4 * 4;
        float r0 = (av.x * zf - z * s_vm[e + 0]
                    + vp.x * s_w0[e + 0] + v0.x * s_w1[e + 0] + vn.x * s_w2[e + 0] + s_bl[e + 0]) * og.x;
        float r1 = (av.y * zf - z * s_vm[e + 1]
                    + vp.y * s_w0[e + 1] + v0.y * s_w1[e + 1] + vn.y * s_w2[e + 1] + s_bl[e + 1]) * og.y;
        float r2 = (av.z * zf - z * s_vm[e + 2]
                    + vp.z * s_w0[e + 2] + v0.z * s_w1[e + 2] + vn.z * s_w2[e + 2] + s_bl[e + 2]) * og.z;
        float r3 = (av.w * zf - z * s_vm[e + 3]
                    + vp.w * s_w0[e + 3] + v0.w * s_w1[e + 3] + vn.w * s_w2[e + 3] + s_bl[e + 3]) * og.w;
        __half h0 = __float2half_rn(r0), h1 = __float2half_rn(r1);
        __half h2 = __float2half_rn(r2), h3 = __float2half_rn(r3);
        __half l0 = __float2half_rn(r0 - __half2float(h0));
        __half l1 = __float2half_rn(r1 - __half2float(h1));
        __half l2 = __float2half_rn(r2 - __half2float(h2));
        __half l3 = __float2half_rn(r3 - __half2float(h3));
        uint2 hw, lw;
        hw.x = ((uint32_t)__half_as_ushort(h1) << 16) | __half_as_ushort(h0);
        hw.y = ((uint32_t)__half_as_ushort(h3) << 16) | __half_as_ushort(h2);
        lw.x = ((uint32_t)__half_as_ushort(l1) << 16) | __half_as_ushort(l0);
        lw.y = ((uint32_t)__half_as_ushort(l3) << 16) | __half_as_ushort(l2);
        *(uint2*)(outp + e) = hw;
        *(uint2*)(outp + 256 + e) = lw;
    }
}

// ---------------- launch ----------------
extern "C" void kernel_launch(void* const* d_in, const int* in_sizes, int n_in,
                              void* d_out, int out_size) {
    const float* x      = (const float*)d_in[0];
    const float* sinp   = (const float*)d_in[1];
    const float* cosp   = (const float*)d_in[2];
    const float* W_qkvo = (const float*)d_in[3];
    const float* b_qkvo = (const float*)d_in[4];
    const float* W_lepe = (const float*)d_in[5];
    const float* b_lepe = (const float*)d_in[6];
    const float* W_proj = (const float*)d_in[7];
    const float* b_proj = (const float*)d_in[8];
    float* out = (float*)d_out;

    __half *xs_p, *ws_p, *tmph_p, *wp_p;
    float* qkvo_p;
    cudaGetSymbolAddress((void**)&qkvo_p, g_qkvo);
    cudaGetSymbolAddress((void**)&xs_p, g_xs);
    cudaGetSymbolAddress((void**)&ws_p, g_ws);
    cudaGetSymbolAddress((void**)&tmph_p, g_tmph);
    cudaGetSymbolAddress((void**)&wp_p, g_wp);

    cudaFuncSetAttribute(gemm_half, cudaFuncAttributeMaxDynamicSharedMemorySize, GEMM_SMEM);

    const int M = BB * SEQ;  // 32768

    // 0) fused splits + zeroing, one launch
    prep_kernel<<<(TTOT + 255) / 256, 256>>>(x, W_qkvo, W_proj);

    // 1) qkvo = x @ W_qkvo^T + b  (HMMA, K=512 split)
    {
        dim3 grid(QKVO / BN, M / BM);
        gemm_half<<<grid, 256, GEMM_SMEM>>>(xs_p, ws_p, b_qkvo, qkvo_p, QKVO);
    }
    // 2) state reduction
    {
        dim3 grid(BB * NH, SEQ / CHUNK);
        reduce_kernel<<<grid, 256>>>(sinp, cosp);
    }
    // 3) attention epilogue (HMMA matvec)
    {
        dim3 grid(SEQ / ATB, BB, NH);
        attn_kernel<<<grid, 128>>>(sinp, cosp, W_lepe, b_lepe);
    }
    // 4) out = tmp @ W_proj^T + b_proj  (HMMA)
    {
        dim3 grid(DIM / BN, M / BM);
        gemm_half<<<grid, 256, GEMM_SMEM>>>(tmph_p, wp_p, b_proj, out, DIM);
    }
}

// round 11
// speedup vs baseline: 1.5755x; 1.1235x over previous
#include <cuda_runtime.h>
#include <cuda_fp16.h>
#include <math.h>
#include <stdint.h>

#define BB 4
#define SEQ 8192
#define DIM 256
#define NH 8
#define HD 32
#define INTERNAL 256
#define QKVO 1024
#define KK 512                      // split K (2 x 256)
#define SCALE_F 0.17677669529663687f
#define S_CONST 0.00464534038f

// ---------------- scratch ----------------
__device__ __align__(16) float g_qkvo[(size_t)BB * SEQ * QKVO];      // 128 MB
__device__ __align__(16) __half g_xs[(size_t)BB * SEQ * KK];         // 32 MB
__device__ __align__(16) __half g_ws[(size_t)QKVO * KK];             // 1 MB
__device__ __align__(16) __half g_tmph[(size_t)BB * SEQ * KK];       // 32 MB
__device__ __align__(16) __half g_wp[(size_t)DIM * KK];              // 256 KB
__device__ float g_kv[BB * NH * HD * HD];
__device__ float g_km[BB * NH * HD];
__device__ float g_vm[BB * NH * HD];

__device__ __forceinline__ float elu1(float x) { return x > 0.f ? x + 1.f : __expf(x); }

__device__ __forceinline__ uint32_t smem_u32(const void* p) {
    return (uint32_t)__cvta_generic_to_shared(p);
}
__device__ __forceinline__ void cpa16(uint32_t dst, const void* src) {
    asm volatile("cp.async.cg.shared.global [%0], [%1], 16;" :: "r"(dst), "l"(src));
}
__device__ __forceinline__ void cpa_commit() {
    asm volatile("cp.async.commit_group;" ::: "memory");
}
template <int N> __device__ __forceinline__ void cpa_wait() {
    asm volatile("cp.async.wait_group %0;" :: "n"(N) : "memory");
}
#define LDSM4(r, a) \
    asm volatile("ldmatrix.sync.aligned.m8n8.x4.shared.b16 {%0,%1,%2,%3}, [%4];" \
                 : "=r"((r)[0]), "=r"((r)[1]), "=r"((r)[2]), "=r"((r)[3]) : "r"(a))
#define MMA16816(d, a, b0, b1) \
    asm volatile("mma.sync.aligned.m16n8k16.row.col.f32.f16.f16.f32 " \
                 "{%0,%1,%2,%3},{%4,%5,%6,%7},{%8,%9},{%0,%1,%2,%3};" \
                 : "+f"((d)[0]), "+f"((d)[1]), "+f"((d)[2]), "+f"((d)[3]) \
                 : "r"((a)[0]), "r"((a)[1]), "r"((a)[2]), "r"((a)[3]), "r"(b0), "r"(b1))

// ---------------- GEMM config: 128x128 CTA, warp tile 32x64, 2 CTAs/SM ----------------
#define BM 128
#define BN 128
#define BK 64
#define NCH (KK / BK)               // 8
#define NSTG 3
#define TILEA (BM * 128)            // 16384 B
#define TILEB (BN * 128)            // 16384 B
#define STGB (TILEA + TILEB)        // 32768 B
#define GEMM_SMEM (NSTG * STGB)     // 98304 B

__device__ __forceinline__ void stage_tiles(uint32_t sb, const __half* Ab,
                                            const __half* Bb, int tid,
                                            int chunk, int buf) {
    const uint32_t ab = sb + buf * STGB;
    const uint32_t bbse = ab + TILEA;
    const __half* Ap = Ab + chunk * BK;
    const __half* Bp = Bb + chunk * BK;
#pragma unroll
    for (int i = 0; i < 4; i++) {
        int line = tid + i * 256;            // 0..1023
        int row = line >> 3, j = line & 7;
        uint32_t sw = row * 128 + ((j ^ (row & 7)) << 4);
        cpa16(ab + sw, Ap + (size_t)row * KK + j * 8);
    }
#pragma unroll
    for (int i = 0; i < 4; i++) {
        int line = tid + i * 256;
        int row = line >> 3, j = line & 7;
        uint32_t sw = row * 128 + ((j ^ (row & 7)) << 4);
        cpa16(bbse + sw, Bp + (size_t)row * KK + j * 8);
    }
    cpa_commit();
}

// C[M,Nn] = A'[M,512]h @ B'[Nn,512]h^T + bias (fp32 accum)
__global__ __launch_bounds__(256, 2)
void gemm_half(const __half* __restrict__ A, const __half* __restrict__ Bm,
               const float* __restrict__ bias, float* __restrict__ C, int Nn) {
    extern __shared__ char smem[];
    const uint32_t sb = smem_u32(smem);
    const int tid = threadIdx.x;
    const int wid = tid >> 5;
    const int lane = tid & 31;
    const int bm = blockIdx.y * BM;
    const int bn = blockIdx.x * BN;
    const int wm0 = (wid & 3) * 32;          // 4 warps in M
    const int wn0 = (wid >> 2) * 64;         // 2 warps in N

    const __half* Ab = A + (size_t)bm * KK;
    const __half* Bb = Bm + (size_t)bn * KK;

    float acc[2][8][4];
#pragma unroll
    for (int i = 0; i < 2; i++)
#pragma unroll
        for (int j = 0; j < 8; j++)
#pragma unroll
            for (int k = 0; k < 4; k++) acc[i][j][k] = 0.f;

    const int lrA = (lane & 7) + ((lane >> 3) & 1) * 8;
    const int lcA = ((lane >> 4) & 1) * 16;
    const int lrB = ((lane >> 4) & 1) * 8 + (lane & 7);
    const int lcB = ((lane >> 3) & 1) * 16;

    stage_tiles(sb, Ab, Bb, tid, 0, 0);
    stage_tiles(sb, Ab, Bb, tid, 1, 1);

    for (int c = 0; c < NCH; c++) {
        if (c + 2 < NCH) cpa_wait<1>(); else cpa_wait<0>();
        __syncthreads();
        if (c + 2 < NCH) stage_tiles(sb, Ab, Bb, tid, c + 2, (c + 2) % NSTG);
        const uint32_t ab = sb + (c % NSTG) * STGB;
        const uint32_t bbse = ab + TILEA;
#pragma unroll
        for (int ks = 0; ks < 4; ks++) {
            uint32_t afr[2][4], bfr[4][4];
#pragma unroll
            for (int mi = 0; mi < 2; mi++) {
                int r = wm0 + mi * 16 + lrA;
                uint32_t cc = (uint32_t)(ks * 32 + lcA);
                LDSM4(afr[mi], ab + r * 128 + (cc ^ ((r & 7) << 4)));
            }
#pragma unroll
            for (int bi = 0; bi < 4; bi++) {
                int r = wn0 + bi * 16 + lrB;
                uint32_t cc = (uint32_t)(ks * 32 + lcB);
                LDSM4(bfr[bi], bbse + r * 128 + (cc ^ ((r & 7) << 4)));
            }
#pragma unroll
            for (int mi = 0; mi < 2; mi++)
#pragma unroll
                for (int nj = 0; nj < 8; nj++)
                    MMA16816(acc[mi][nj], afr[mi],
                             bfr[nj >> 1][(nj & 1) * 2], bfr[nj >> 1][(nj & 1) * 2 + 1]);
        }
    }

    const int g = lane >> 2, t4 = lane & 3;
#pragma unroll
    for (int mi = 0; mi < 2; mi++) {
#pragma unroll
        for (int nj = 0; nj < 8; nj++) {
            const int col = bn + wn0 + nj * 8 + t4 * 2;
            const float2 bv = *(const float2*)(bias + col);
            const int row0 = bm + wm0 + mi * 16 + g;
            float2 o0 = {acc[mi][nj][0] + bv.x, acc[mi][nj][1] + bv.y};
            float2 o1 = {acc[mi][nj][2] + bv.x, acc[mi][nj][3] + bv.y};
            *(float2*)(C + (size_t)row0 * Nn + col) = o0;
            *(float2*)(C + (size_t)(row0 + 8) * Nn + col) = o1;
        }
    }
}

// ---------------- fused prep: all splits + accumulator zeroing, one launch ----------------
#define TX (BB * SEQ * DIM)         // 8388608
#define TW (QKVO * DIM)             // 262144
#define TP (DIM * DIM)              // 65536
#define NKV (BB * NH * HD * HD)     // 32768
#define NKM (BB * NH * HD)          // 1024
#define TTOT (TX + TW + TP + NKV + 2 * NKM)

__global__ void prep_kernel(const float* __restrict__ x,
                            const float* __restrict__ W_qkvo,
                            const float* __restrict__ W_proj) {
    int i = blockIdx.x * 256 + threadIdx.x;
    if (i >= TTOT) return;
    if (i < TX) {
        int row = i >> 8, c = i & 255;
        float v = x[i];
        __half hi = __float2half_rn(v);
        __half lo = __float2half_rn(v - __half2float(hi));
        size_t base = (size_t)row * KK + c;
        g_xs[base] = hi;
        g_xs[base + 256] = lo;               // A operand: [hi | lo]
    } else if (i < TX + TW) {
        int k = i - TX;
        int row = k >> 8, c = k & 255;
        float v = W_qkvo[k];
        __half hi = __float2half_rn(v);
        size_t base = (size_t)row * KK + c;
        g_ws[base] = hi;
        g_ws[base + 256] = hi;               // B operand: [hi | hi]
    } else if (i < TX + TW + TP) {
        int k = i - TX - TW;
        int row = k >> 8, c = k & 255;
        float v = W_proj[k];
        __half hi = __float2half_rn(v);
        size_t base = (size_t)row * KK + c;
        g_wp[base] = hi;
        g_wp[base + 256] = hi;
    } else {
        int k = i - TX - TW - TP;
        if (k < NKV) g_kv[k] = 0.f;
        else if (k < NKV + NKM) g_km[k - NKV] = 0.f;
        else g_vm[k - NKV - NKM] = 0.f;
    }
}

// ---------------- per-(b,h) state reduction: double-buffered, 1 sync / 8 tokens ----------
#define CHUNK 512
#define NIT (CHUNK / 8)
__global__ __launch_bounds__(256)
void reduce_kernel(const float* __restrict__ sinp, const float* __restrict__ cosp) {
    const int bh = blockIdx.x;
    const int chunk = blockIdx.y;
    const int b = bh / NH, h = bh % NH;
    const int tid = threadIdx.x;
    const int j = tid >> 5;                  // token sub 0..7
    const int d = tid & 31;
    const int dbase = j * 4;
    __shared__ float s_ks[2][8][32];
    __shared__ float s_vs[2][8][32];
    float acc[4] = {0.f, 0.f, 0.f, 0.f};
    float ksum = 0.f, vsum = 0.f;
    const int n0 = chunk * CHUNK;
    const float sgn = (d & 1) ? 1.f : -1.f;
    const size_t kcol = INTERNAL + h * HD;
    const size_t vcol = 2 * INTERNAL + h * HD;

    {
        const int n = n0 + j;
        const size_t row = ((size_t)b * SEQ + n) * QKVO;
        const float kh  = elu1(g_qkvo[row + kcol + d]);
        const float khp = elu1(g_qkvo[row + kcol + (d ^ 1)]);
        const float vv  = g_qkvo[row + vcol + d];
        const float sn = sinp[n * HD + d];
        const float cs = cosp[n * HD + d];
        s_ks[0][j][d] = (kh * cs + sgn * khp * sn) * S_CONST;
        s_vs[0][j][d] = vv * S_CONST;
        ksum += kh;
        vsum += vv;
    }
    __syncthreads();

    for (int it = 0; it < NIT; it++) {
        const int bsel = it & 1;
        float nk = 0.f, nkp = 0.f, nv = 0.f, nsn = 0.f, ncs = 0.f;
        const bool more = (it + 1 < NIT);
        if (more) {
            const int n = n0 + (it + 1) * 8 + j;
            const size_t row = ((size_t)b * SEQ + n) * QKVO;
            nk  = g_qkvo[row + kcol + d];
            nkp = g_qkvo[row + kcol + (d ^ 1)];
            nv  = g_qkvo[row + vcol + d];
            nsn = sinp[n * HD + d];
            ncs = cosp[n * HD + d];
        }
#pragma unroll
        for (int jj = 0; jj < 8; jj++) {
            const float vv = s_vs[bsel][jj][d];
#pragma unroll
            for (int dd = 0; dd < 4; dd++)
                acc[dd] += s_ks[bsel][jj][dbase + dd] * vv;
        }
        if (more) {
            const float kh = elu1(nk);
            const float khp = elu1(nkp);
            s_ks[bsel ^ 1][j][d] = (kh * ncs + sgn * khp * nsn) * S_CONST;
            s_vs[bsel ^ 1][j][d] = nv * S_CONST;
            ksum += kh;
            vsum += nv;
        }
        __syncthreads();
    }
#pragma unroll
    for (int dd = 0; dd < 4; dd++)
        atomicAdd(&g_kv[(bh * HD + dbase + dd) * HD + d], acc[dd]);
    atomicAdd(&g_km[bh * HD + d], ksum);
    atomicAdd(&g_vm[bh * HD + d], vsum);
}

// ---------------- attn epilogue: coalesced full-row layout, all heads per block --------
// block = 256 threads = 4 tokens x 64 channel-quads; loops over ATOKS tokens
#define ATOKS 32
#define APASS (ATOKS / 4)
__global__ __launch_bounds__(256)
void attn_kernel(const float* __restrict__ sinp, const float* __restrict__ cosp,
                 const float* __restrict__ W_lepe, const float* __restrict__ b_lepe) {
    const int b = blockIdx.y;
    const int n0 = blockIdx.x * ATOKS;
    const int tid = threadIdx.x;
    const int cq = tid & 63;                 // channel quad 0..63
    const int tok = tid >> 6;                // 0..3
    const int h = cq >> 3;                   // head
    const int eq = cq & 7;                   // quad within head
    const int c0 = cq * 4;                   // channel base (0..252)
    const int d0 = eq * 4;                   // head-dim base (= c0 & 31)

    __shared__ __align__(16) float s_kv[NH][HD][36];   // 36864 B, conflict-free f4 rows
    __shared__ __align__(16) float s_qs[4][NH * 36];   // 4608 B
    __shared__ float s_km[INTERNAL], s_vm[INTERNAL];
    __shared__ float s_w0[INTERNAL], s_w1[INTERNAL], s_w2[INTERNAL], s_bl[INTERNAL];

    // stage kv for all 8 heads (g_kv contiguous per b): s_kv[h][d][e]
    for (int i = tid; i < NH * HD * HD; i += 256) {
        const int hh = i >> 10, rem = i & 1023;
        s_kv[hh][rem >> 5][rem & 31] = g_kv[b * NH * HD * HD + i];
    }
    {
        const int c = tid;                   // 256 threads = all channels
        const int bh = b * NH + (c >> 5);
        const int d = c & 31;
        const float invN = 1.f / (float)SEQ;
        s_km[c] = g_km[bh * HD + d] * invN;
        s_vm[c] = g_vm[bh * HD + d] * invN;
        s_w0[c] = W_lepe[c * 3 + 0];
        s_w1[c] = W_lepe[c * 3 + 1];
        s_w2[c] = W_lepe[c * 3 + 2];
        s_bl[c] = b_lepe[c];
    }
    __syncthreads();

    const unsigned FM = 0xffffffffu;

    for (int p = 0; p < APASS; p++) {
        const int n = n0 + p * 4 + tok;
        const size_t row = ((size_t)b * SEQ + n) * QKVO;

        // q quad (coalesced: warp reads 512B contiguous)
        const float4 qv = *(const float4*)(g_qkvo + row + c0);
        const float qh0 = elu1(qv.x), qh1 = elu1(qv.y);
        const float qh2 = elu1(qv.z), qh3 = elu1(qv.w);

        // z over this head's 32 channels (8-lane group reduce)
        float zp = qh0 * s_km[c0] + qh1 * s_km[c0 + 1] + qh2 * s_km[c0 + 2] + qh3 * s_km[c0 + 3];
        zp += __shfl_xor_sync(FM, zp, 1);
        zp += __shfl_xor_sync(FM, zp, 2);
        zp += __shfl_xor_sync(FM, zp, 4);
        const float z = zp * SCALE_F;

        // theta shift (pairs in-quad)
        const float4 sn4 = *(const float4*)(sinp + (size_t)n * HD + d0);
        const float4 cs4 = *(const float4*)(cosp + (size_t)n * HD + d0);
        const float qs0 = qh0 * cs4.x - qh1 * sn4.x;
        const float qs1 = qh1 * cs4.y + qh0 * sn4.y;
        const float qs2 = qh2 * cs4.z - qh3 * sn4.z;
        const float qs3 = qh3 * cs4.w + qh2 * sn4.w;

        __syncthreads();                     // prior pass done reading s_qs
        *(float4*)(&s_qs[tok][h * 36 + d0]) = make_float4(qs0, qs1, qs2, qs3);
        __syncthreads();

        // matvec: acc[e-quad] = sum_d qs[d] * kv[d][e]
        float a0 = 0.f, a1 = 0.f, a2 = 0.f, a3 = 0.f;
#pragma unroll
        for (int u = 0; u < 8; u++) {
            const float4 q4 = *(const float4*)(&s_qs[tok][h * 36 + u * 4]);
            const float4 k0 = *(const float4*)(&s_kv[h][u * 4 + 0][d0]);
            const float4 k1 = *(const float4*)(&s_kv[h][u * 4 + 1][d0]);
            const float4 k2 = *(const float4*)(&s_kv[h][u * 4 + 2][d0]);
            const float4 k3 = *(const float4*)(&s_kv[h][u * 4 + 3][d0]);
            a0 += q4.x * k0.x + q4.y * k1.x + q4.z * k2.x + q4.w * k3.x;
            a1 += q4.x * k0.y + q4.y * k1.y + q4.z * k2.y + q4.w * k3.y;
            a2 += q4.x * k0.z + q4.y * k1.z + q4.z * k2.z + q4.w * k3.z;
            a3 += q4.x * k0.w + q4.y * k1.w + q4.z * k2.w + q4.w * k3.w;
        }

        // MALA correction + lepe + o-gate (all coalesced)
        const float zf = 1.f + 1.f / (z + 1e-6f);
        const float* vrow = g_qkvo + row + 2 * INTERNAL + c0;
        const float4 v0 = *(const float4*)(vrow);
        const float4 vp = (n > 0) ? *(const float4*)(vrow - QKVO) : make_float4(0, 0, 0, 0);
        const float4 vn = (n < SEQ - 1) ? *(const float4*)(vrow + QKVO) : make_float4(0, 0, 0, 0);
        const float4 og = *(const float4*)(g_qkvo + row + 3 * INTERNAL + c0);

        const float r0 = (a0 * zf - z * s_vm[c0 + 0]
                    + vp.x * s_w0[c0 + 0] + v0.x * s_w1[c0 + 0] + vn.x * s_w2[c0 + 0] + s_bl[c0 + 0]) * og.x;
        const float r1 = (a1 * zf - z * s_vm[c0 + 1]
                    + vp.y * s_w0[c0 + 1] + v0.y * s_w1[c0 + 1] + vn.y * s_w2[c0 + 1] + s_bl[c0 + 1]) * og.y;
        const float r2 = (a2 * zf - z * s_vm[c0 + 2]
                    + vp.z * s_w0[c0 + 2] + v0.z * s_w1[c0 + 2] + vn.z * s_w2[c0 + 2] + s_bl[c0 + 2]) * og.z;
        const float r3 = (a3 * zf - z * s_vm[c0 + 3]
                    + vp.w * s_w0[c0 + 3] + v0.w * s_w1[c0 + 3] + vn.w * s_w2[c0 + 3] + s_bl[c0 + 3]) * og.w;

        const __half h0 = __float2half_rn(r0), h1 = __float2half_rn(r1);
        const __half h2 = __float2half_rn(r2), h3 = __float2half_rn(r3);
        const __half l0 = __float2half_rn(r0 - __half2float(h0));
        const __half l1 = __float2half_rn(r1 - __half2float(h1));
        const __half l2 = __float2half_rn(r2 - __half2float(h2));
        const __half l3 = __float2half_rn(r3 - __half2float(h3));
        uint2 hw, lw;
        hw.x = ((uint32_t)__half_as_ushort(h1) << 16) | __half_as_ushort(h0);
        hw.y = ((uint32_t)__half_as_ushort(h3) << 16) | __half_as_ushort(h2);
        lw.x = ((uint32_t)__half_as_ushort(l1) << 16) | __half_as_ushort(l0);
        lw.y = ((uint32_t)__half_as_ushort(l3) << 16) | __half_as_ushort(l2);
        __half* outp = g_tmph + ((size_t)b * SEQ + n) * KK + c0;
        *(uint2*)(outp) = hw;                // hi: warp writes 256B contiguous
        *(uint2*)(outp + 256) = lw;          // lo: ditto
    }
}

// ---------------- launch ----------------
extern "C" void kernel_launch(void* const* d_in, const int* in_sizes, int n_in,
                              void* d_out, int out_size) {
    const float* x      = (const float*)d_in[0];
    const float* sinp   = (const float*)d_in[1];
    const float* cosp   = (const float*)d_in[2];
    const float* W_qkvo = (const float*)d_in[3];
    const float* b_qkvo = (const float*)d_in[4];
    const float* W_lepe = (const float*)d_in[5];
    const float* b_lepe = (const float*)d_in[6];
    const float* W_proj = (const float*)d_in[7];
    const float* b_proj = (const float*)d_in[8];
    float* out = (float*)d_out;

    __half *xs_p, *ws_p, *tmph_p, *wp_p;
    float* qkvo_p;
    cudaGetSymbolAddress((void**)&qkvo_p, g_qkvo);
    cudaGetSymbolAddress((void**)&xs_p, g_xs);
    cudaGetSymbolAddress((void**)&ws_p, g_ws);
    cudaGetSymbolAddress((void**)&tmph_p, g_tmph);
    cudaGetSymbolAddress((void**)&wp_p, g_wp);

    cudaFuncSetAttribute(gemm_half, cudaFuncAttributeMaxDynamicSharedMemorySize, GEMM_SMEM);

    const int M = BB * SEQ;  // 32768

    // 0) fused splits + zeroing, one launch
    prep_kernel<<<(TTOT + 255) / 256, 256>>>(x, W_qkvo, W_proj);

    // 1) qkvo = x @ W_qkvo^T + b  (HMMA, K=512 split)
    {
        dim3 grid(QKVO / BN, M / BM);
        gemm_half<<<grid, 256, GEMM_SMEM>>>(xs_p, ws_p, b_qkvo, qkvo_p, QKVO);
    }
    // 2) state reduction
    {
        dim3 grid(BB * NH, SEQ / CHUNK);
        reduce_kernel<<<grid, 256>>>(sinp, cosp);
    }
    // 3) attention epilogue (coalesced, all heads per block)
    {
        dim3 grid(SEQ / ATOKS, BB);
        attn_kernel<<<grid, 256>>>(sinp, cosp, W_lepe, b_lepe);
    }
    // 4) out = tmp @ W_proj^T + b_proj  (HMMA)
    {
        dim3 grid(DIM / BN, M / BM);
        gemm_half<<<grid, 256, GEMM_SMEM>>>(tmph_p, wp_p, b_proj, out, DIM);
    }
}

// round 13
// speedup vs baseline: 1.5790x; 1.0023x over previous
#include <cuda_runtime.h>
#include <cuda_fp16.h>
#include <math.h>
#include <stdint.h>

#define BB 4
#define SEQ 8192
#define DIM 256
#define NH 8
#define HD 32
#define INTERNAL 256
#define QKVO 1024
#define KK 512                      // split K (2 x 256)
#define SCALE_F 0.17677669529663687f
#define S_CONST 0.00464534038f

// ---------------- scratch ----------------
__device__ __align__(16) float g_qkvo[(size_t)BB * SEQ * QKVO];      // 128 MB
__device__ __align__(16) __half g_xs[(size_t)BB * SEQ * KK];         // 32 MB
__device__ __align__(16) __half g_ws[(size_t)QKVO * KK];             // 1 MB
__device__ __align__(16) __half g_tmph[(size_t)BB * SEQ * KK];       // 32 MB
__device__ __align__(16) __half g_wp[(size_t)DIM * KK];              // 256 KB
__device__ float g_kv[BB * NH * HD * HD];
__device__ float g_km[BB * NH * HD];
__device__ float g_vm[BB * NH * HD];

__device__ __forceinline__ float elu1(float x) { return x > 0.f ? x + 1.f : __expf(x); }

__device__ __forceinline__ uint32_t smem_u32(const void* p) {
    return (uint32_t)__cvta_generic_to_shared(p);
}
__device__ __forceinline__ void cpa16(uint32_t dst, const void* src) {
    asm volatile("cp.async.cg.shared.global [%0], [%1], 16;" :: "r"(dst), "l"(src));
}
__device__ __forceinline__ void cpa_commit() {
    asm volatile("cp.async.commit_group;" ::: "memory");
}
template <int N> __device__ __forceinline__ void cpa_wait() {
    asm volatile("cp.async.wait_group %0;" :: "n"(N) : "memory");
}
#define LDSM4(r, a) \
    asm volatile("ldmatrix.sync.aligned.m8n8.x4.shared.b16 {%0,%1,%2,%3}, [%4];" \
                 : "=r"((r)[0]), "=r"((r)[1]), "=r"((r)[2]), "=r"((r)[3]) : "r"(a))
#define MMA16816(d, a, b0, b1) \
    asm volatile("mma.sync.aligned.m16n8k16.row.col.f32.f16.f16.f32 " \
                 "{%0,%1,%2,%3},{%4,%5,%6,%7},{%8,%9},{%0,%1,%2,%3};" \
                 : "+f"((d)[0]), "+f"((d)[1]), "+f"((d)[2]), "+f"((d)[3]) \
                 : "r"((a)[0]), "r"((a)[1]), "r"((a)[2]), "r"((a)[3]), "r"(b0), "r"(b1))

// ---------------- GEMM config: 128x128 CTA, warp tile 32x64, 2 CTAs/SM ----------------
#define BM 128
#define BN 128
#define BK 64
#define NCH (KK / BK)               // 8
#define NSTG 3
#define TILEA (BM * 128)            // 16384 B
#define TILEB (BN * 128)            // 16384 B
#define STGB (TILEA + TILEB)        // 32768 B
#define GEMM_SMEM (NSTG * STGB)     // 98304 B

__device__ __forceinline__ void stage_tiles(uint32_t sb, const __half* Ab,
                                            const __half* Bb, int tid,
                                            int chunk, int buf) {
    const uint32_t ab = sb + buf * STGB;
    const uint32_t bbse = ab + TILEA;
    const __half* Ap = Ab + chunk * BK;
    const __half* Bp = Bb + chunk * BK;
#pragma unroll
    for (int i = 0; i < 4; i++) {
        int line = tid + i * 256;            // 0..1023
        int row = line >> 3, j = line & 7;
        uint32_t sw = row * 128 + ((j ^ (row & 7)) << 4);
        cpa16(ab + sw, Ap + (size_t)row * KK + j * 8);
    }
#pragma unroll
    for (int i = 0; i < 4; i++) {
        int line = tid + i * 256;
        int row = line >> 3, j = line & 7;
        uint32_t sw = row * 128 + ((j ^ (row & 7)) << 4);
        cpa16(bbse + sw, Bp + (size_t)row * KK + j * 8);
    }
    cpa_commit();
}

// C[M,Nn] = A'[M,512]h @ B'[Nn,512]h^T + bias (fp32 accum)
__global__ __launch_bounds__(256, 2)
void gemm_half(const __half* __restrict__ A, const __half* __restrict__ Bm,
               const float* __restrict__ bias, float* __restrict__ C, int Nn) {
    extern __shared__ char smem[];
    const uint32_t sb = smem_u32(smem);
    const int tid = threadIdx.x;
    const int wid = tid >> 5;
    const int lane = tid & 31;
    const int bm = blockIdx.y * BM;
    const int bn = blockIdx.x * BN;
    const int wm0 = (wid & 3) * 32;          // 4 warps in M
    const int wn0 = (wid >> 2) * 64;         // 2 warps in N

    const __half* Ab = A + (size_t)bm * KK;
    const __half* Bb = Bm + (size_t)bn * KK;

    float acc[2][8][4];
#pragma unroll
    for (int i = 0; i < 2; i++)
#pragma unroll
        for (int j = 0; j < 8; j++)
#pragma unroll
            for (int k = 0; k < 4; k++) acc[i][j][k] = 0.f;

    const int lrA = (lane & 7) + ((lane >> 3) & 1) * 8;
    const int lcA = ((lane >> 4) & 1) * 16;
    const int lrB = ((lane >> 4) & 1) * 8 + (lane & 7);
    const int lcB = ((lane >> 3) & 1) * 16;

    stage_tiles(sb, Ab, Bb, tid, 0, 0);
    stage_tiles(sb, Ab, Bb, tid, 1, 1);

    for (int c = 0; c < NCH; c++) {
        if (c + 2 < NCH) cpa_wait<1>(); else cpa_wait<0>();
        __syncthreads();
        if (c + 2 < NCH) stage_tiles(sb, Ab, Bb, tid, c + 2, (c + 2) % NSTG);
        const uint32_t ab = sb + (c % NSTG) * STGB;
        const uint32_t bbse = ab + TILEA;
#pragma unroll
        for (int ks = 0; ks < 4; ks++) {
            uint32_t afr[2][4], bfr[4][4];
#pragma unroll
            for (int mi = 0; mi < 2; mi++) {
                int r = wm0 + mi * 16 + lrA;
                uint32_t cc = (uint32_t)(ks * 32 + lcA);
                LDSM4(afr[mi], ab + r * 128 + (cc ^ ((r & 7) << 4)));
            }
#pragma unroll
            for (int bi = 0; bi < 4; bi++) {
                int r = wn0 + bi * 16 + lrB;
                uint32_t cc = (uint32_t)(ks * 32 + lcB);
                LDSM4(bfr[bi], bbse + r * 128 + (cc ^ ((r & 7) << 4)));
            }
#pragma unroll
            for (int mi = 0; mi < 2; mi++)
#pragma unroll
                for (int nj = 0; nj < 8; nj++)
                    MMA16816(acc[mi][nj], afr[mi],
                             bfr[nj >> 1][(nj & 1) * 2], bfr[nj >> 1][(nj & 1) * 2 + 1]);
        }
    }

    const int g = lane >> 2, t4 = lane & 3;
#pragma unroll
    for (int mi = 0; mi < 2; mi++) {
#pragma unroll
        for (int nj = 0; nj < 8; nj++) {
            const int col = bn + wn0 + nj * 8 + t4 * 2;
            const float2 bv = *(const float2*)(bias + col);
            const int row0 = bm + wm0 + mi * 16 + g;
            float2 o0 = {acc[mi][nj][0] + bv.x, acc[mi][nj][1] + bv.y};
            float2 o1 = {acc[mi][nj][2] + bv.x, acc[mi][nj][3] + bv.y};
            *(float2*)(C + (size_t)row0 * Nn + col) = o0;
            *(float2*)(C + (size_t)(row0 + 8) * Nn + col) = o1;
        }
    }
}

// ---------------- fused prep: all splits + accumulator zeroing, one launch ----------------
#define TX (BB * SEQ * DIM)         // 8388608
#define TW (QKVO * DIM)             // 262144
#define TP (DIM * DIM)              // 65536
#define NKV (BB * NH * HD * HD)     // 32768
#define NKM (BB * NH * HD)          // 1024
#define TTOT (TX + TW + TP + NKV + 2 * NKM)

__global__ void prep_kernel(const float* __restrict__ x,
                            const float* __restrict__ W_qkvo,
                            const float* __restrict__ W_proj) {
    int i = blockIdx.x * 256 + threadIdx.x;
    if (i >= TTOT) return;
    if (i < TX) {
        int row = i >> 8, c = i & 255;
        float v = x[i];
        __half hi = __float2half_rn(v);
        __half lo = __float2half_rn(v - __half2float(hi));
        size_t base = (size_t)row * KK + c;
        g_xs[base] = hi;
        g_xs[base + 256] = lo;               // A operand: [hi | lo]
    } else if (i < TX + TW) {
        int k = i - TX;
        int row = k >> 8, c = k & 255;
        float v = W_qkvo[k];
        __half hi = __float2half_rn(v);
        size_t base = (size_t)row * KK + c;
        g_ws[base] = hi;
        g_ws[base + 256] = hi;               // B operand: [hi | hi]
    } else if (i < TX + TW + TP) {
        int k = i - TX - TW;
        int row = k >> 8, c = k & 255;
        float v = W_proj[k];
        __half hi = __float2half_rn(v);
        size_t base = (size_t)row * KK + c;
        g_wp[base] = hi;
        g_wp[base + 256] = hi;
    } else {
        int k = i - TX - TW - TP;
        if (k < NKV) g_kv[k] = 0.f;
        else if (k < NKV + NKM) g_km[k - NKV] = 0.f;
        else g_vm[k - NKV - NKM] = 0.f;
    }
}

// ---------------- per-(b,h) state reduction: double-buffered, 1 sync / 8 tokens ----------
#define CHUNK 512
#define NIT (CHUNK / 8)
__global__ __launch_bounds__(256)
void reduce_kernel(const float* __restrict__ sinp, const float* __restrict__ cosp) {
    const int bh = blockIdx.x;
    const int chunk = blockIdx.y;
    const int b = bh / NH, h = bh % NH;
    const int tid = threadIdx.x;
    const int j = tid >> 5;                  // token sub 0..7
    const int d = tid & 31;
    const int dbase = j * 4;
    __shared__ float s_ks[2][8][32];
    __shared__ float s_vs[2][8][32];
    float acc[4] = {0.f, 0.f, 0.f, 0.f};
    float ksum = 0.f, vsum = 0.f;
    const int n0 = chunk * CHUNK;
    const float sgn = (d & 1) ? 1.f : -1.f;
    const size_t kcol = INTERNAL + h * HD;
    const size_t vcol = 2 * INTERNAL + h * HD;

    {
        const int n = n0 + j;
        const size_t row = ((size_t)b * SEQ + n) * QKVO;
        const float kh  = elu1(g_qkvo[row + kcol + d]);
        const float khp = elu1(g_qkvo[row + kcol + (d ^ 1)]);
        const float vv  = g_qkvo[row + vcol + d];
        const float sn = sinp[n * HD + d];
        const float cs = cosp[n * HD + d];
        s_ks[0][j][d] = (kh * cs + sgn * khp * sn) * S_CONST;
        s_vs[0][j][d] = vv * S_CONST;
        ksum += kh;
        vsum += vv;
    }
    __syncthreads();

    for (int it = 0; it < NIT; it++) {
        const int bsel = it & 1;
        float nk = 0.f, nkp = 0.f, nv = 0.f, nsn = 0.f, ncs = 0.f;
        const bool more = (it + 1 < NIT);
        if (more) {
            const int n = n0 + (it + 1) * 8 + j;
            const size_t row = ((size_t)b * SEQ + n) * QKVO;
            nk  = g_qkvo[row + kcol + d];
            nkp = g_qkvo[row + kcol + (d ^ 1)];
            nv  = g_qkvo[row + vcol + d];
            nsn = sinp[n * HD + d];
            ncs = cosp[n * HD + d];
        }
#pragma unroll
        for (int jj = 0; jj < 8; jj++) {
            const float vv = s_vs[bsel][jj][d];
#pragma unroll
            for (int dd = 0; dd < 4; dd++)
                acc[dd] += s_ks[bsel][jj][dbase + dd] * vv;
        }
        if (more) {
            const float kh = elu1(nk);
            const float khp = elu1(nkp);
            s_ks[bsel ^ 1][j][d] = (kh * ncs + sgn * khp * nsn) * S_CONST;
            s_vs[bsel ^ 1][j][d] = nv * S_CONST;
            ksum += kh;
            vsum += nv;
        }
        __syncthreads();
    }
#pragma unroll
    for (int dd = 0; dd < 4; dd++)
        atomicAdd(&g_kv[(bh * HD + dbase + dd) * HD + d], acc[dd]);
    atomicAdd(&g_km[bh * HD + d], ksum);
    atomicAdd(&g_vm[bh * HD + d], vsum);
}

// ---------------- attn epilogue: coalesced + 4 tokens/thread (kv LDS amortized) --------
// block = 256 threads = 4 token-groups x 64 channel-quads; each thread: 4 tokens/pass
#define ATOKS 64
#define NPASS (ATOKS / 16)
__global__ __launch_bounds__(256)
void attn_kernel(const float* __restrict__ sinp, const float* __restrict__ cosp,
                 const float* __restrict__ W_lepe, const float* __restrict__ b_lepe) {
    const int b = blockIdx.y;
    const int n0 = blockIdx.x * ATOKS;
    const int tid = threadIdx.x;
    const int tg = tid >> 6;                 // token group 0..3
    const int cq = tid & 63;                 // channel quad 0..63
    const int h = cq >> 3;
    const int eq = cq & 7;
    const int c0 = cq * 4;
    const int d0 = eq * 4;

    __shared__ __align__(16) float s_kv[NH][HD][36];   // 36864 B
    __shared__ __align__(16) float s_qs[16][NH * 36];  // 18432 B
    __shared__ float s_km[INTERNAL], s_vm[INTERNAL];
    __shared__ float s_w0[INTERNAL], s_w1[INTERNAL], s_w2[INTERNAL], s_bl[INTERNAL];

    for (int i = tid; i < NH * HD * HD; i += 256) {
        const int hh = i >> 10, rem = i & 1023;
        s_kv[hh][rem >> 5][rem & 31] = g_kv[b * NH * HD * HD + i];
    }
    {
        const int c = tid;
        const int bh = b * NH + (c >> 5);
        const int d = c & 31;
        const float invN = 1.f / (float)SEQ;
        s_km[c] = g_km[bh * HD + d] * invN;
        s_vm[c] = g_vm[bh * HD + d] * invN;
        s_w0[c] = W_lepe[c * 3 + 0];
        s_w1[c] = W_lepe[c * 3 + 1];
        s_w2[c] = W_lepe[c * 3 + 2];
        s_bl[c] = b_lepe[c];
    }
    __syncthreads();

    const unsigned FM = 0xffffffffu;
    const float km0 = s_km[c0], km1 = s_km[c0 + 1], km2 = s_km[c0 + 2], km3 = s_km[c0 + 3];
    const float vm0 = s_vm[c0], vm1 = s_vm[c0 + 1], vm2 = s_vm[c0 + 2], vm3 = s_vm[c0 + 3];
    const float w00 = s_w0[c0], w01 = s_w0[c0 + 1], w02 = s_w0[c0 + 2], w03 = s_w0[c0 + 3];
    const float w10 = s_w1[c0], w11 = s_w1[c0 + 1], w12 = s_w1[c0 + 2], w13 = s_w1[c0 + 3];
    const float w20 = s_w2[c0], w21 = s_w2[c0 + 1], w22 = s_w2[c0 + 2], w23 = s_w2[c0 + 3];
    const float bl0 = s_bl[c0], bl1 = s_bl[c0 + 1], bl2 = s_bl[c0 + 2], bl3 = s_bl[c0 + 3];

    for (int p = 0; p < NPASS; p++) {
        const int nbase = n0 + p * 16 + tg * 4;         // this thread's 4 tokens
        const size_t row0 = ((size_t)b * SEQ + nbase) * QKVO;
        float z[4];

        if (p) __syncthreads();              // prior pass matvec done reading s_qs
        // phase A: elu, z, theta-shift, write qs
#pragma unroll
        for (int t = 0; t < 4; t++) {
            const int n = nbase + t;
            const size_t row = row0 + (size_t)t * QKVO;
            const float4 qv = *(const float4*)(g_qkvo + row + c0);
            const float qh0 = elu1(qv.x), qh1 = elu1(qv.y);
            const float qh2 = elu1(qv.z), qh3 = elu1(qv.w);
            float zp = qh0 * km0 + qh1 * km1 + qh2 * km2 + qh3 * km3;
            zp += __shfl_xor_sync(FM, zp, 1);
            zp += __shfl_xor_sync(FM, zp, 2);
            zp += __shfl_xor_sync(FM, zp, 4);
            z[t] = zp * SCALE_F;
            const float4 sn4 = *(const float4*)(sinp + (size_t)n * HD + d0);
            const float4 cs4 = *(const float4*)(cosp + (size_t)n * HD + d0);
            float4 qs;
            qs.x = qh0 * cs4.x - qh1 * sn4.x;
            qs.y = qh1 * cs4.y + qh0 * sn4.y;
            qs.z = qh2 * cs4.z - qh3 * sn4.z;
            qs.w = qh3 * cs4.w + qh2 * sn4.w;
            *(float4*)(&s_qs[tg * 4 + t][h * 36 + d0]) = qs;
        }
        __syncthreads();

        // phase B: matvec, kv quads amortized over 4 tokens
        float a[4][4];
#pragma unroll
        for (int t = 0; t < 4; t++)
#pragma unroll
            for (int e = 0; e < 4; e++) a[t][e] = 0.f;
#pragma unroll
        for (int u = 0; u < 8; u++) {
            const float4 k0 = *(const float4*)(&s_kv[h][u * 4 + 0][d0]);
            const float4 k1 = *(const float4*)(&s_kv[h][u * 4 + 1][d0]);
            const float4 k2 = *(const float4*)(&s_kv[h][u * 4 + 2][d0]);
            const float4 k3 = *(const float4*)(&s_kv[h][u * 4 + 3][d0]);
#pragma unroll
            for (int t = 0; t < 4; t++) {
                const float4 q4 = *(const float4*)(&s_qs[tg * 4 + t][h * 36 + u * 4]);
                a[t][0] += q4.x * k0.x + q4.y * k1.x + q4.z * k2.x + q4.w * k3.x;
                a[t][1] += q4.x * k0.y + q4.y * k1.y + q4.z * k2.y + q4.w * k3.y;
                a[t][2] += q4.x * k0.z + q4.y * k1.z + q4.z * k2.z + q4.w * k3.z;
                a[t][3] += q4.x * k0.w + q4.y * k1.w + q4.z * k2.w + q4.w * k3.w;
            }
        }

        // phase C: epilogue, v-stencil chained in registers
        float4 v[4];
#pragma unroll
        for (int t = 0; t < 4; t++)
            v[t] = *(const float4*)(g_qkvo + row0 + (size_t)t * QKVO + 2 * INTERNAL + c0);
        const float4 vprev = (nbase > 0)
            ? *(const float4*)(g_qkvo + row0 - QKVO + 2 * INTERNAL + c0) : make_float4(0, 0, 0, 0);
        const float4 vnext = (nbase + 4 < SEQ)
            ? *(const float4*)(g_qkvo + row0 + 4 * QKVO + 2 * INTERNAL + c0) : make_float4(0, 0, 0, 0);

#pragma unroll
        for (int t = 0; t < 4; t++) {
            const size_t row = row0 + (size_t)t * QKVO;
            const float4 vp = (t == 0) ? vprev : v[t - 1];
            const float4 vn = (t == 3) ? vnext : v[t + 1];
            const float4 og = *(const float4*)(g_qkvo + row + 3 * INTERNAL + c0);
            const float zt = z[t];
            const float zf = 1.f + 1.f / (zt + 1e-6f);
            const float r0 = (a[t][0] * zf - zt * vm0
                        + vp.x * w00 + v[t].x * w10 + vn.x * w20 + bl0) * og.x;
            const float r1 = (a[t][1] * zf - zt * vm1
                        + vp.y * w01 + v[t].y * w11 + vn.y * w21 + bl1) * og.y;
            const float r2 = (a[t][2] * zf - zt * vm2
                        + vp.z * w02 + v[t].z * w12 + vn.z * w22 + bl2) * og.z;
            const float r3 = (a[t][3] * zf - zt * vm3
                        + vp.w * w03 + v[t].w * w13 + vn.w * w23 + bl3) * og.w;
            const __half h0 = __float2half_rn(r0), h1 = __float2half_rn(r1);
            const __half h2 = __float2half_rn(r2), h3 = __float2half_rn(r3);
            const __half l0 = __float2half_rn(r0 - __half2float(h0));
            const __half l1 = __float2half_rn(r1 - __half2float(h1));
            const __half l2 = __float2half_rn(r2 - __half2float(h2));
            const __half l3 = __float2half_rn(r3 - __half2float(h3));
            uint2 hw, lw;
            hw.x = ((uint32_t)__half_as_ushort(h1) << 16) | __half_as_ushort(h0);
            hw.y = ((uint32_t)__half_as_ushort(h3) << 16) | __half_as_ushort(h2);
            lw.x = ((uint32_t)__half_as_ushort(l1) << 16) | __half_as_ushort(l0);
            lw.y = ((uint32_t)__half_as_ushort(l3) << 16) | __half_as_ushort(l2);
            __half* outp = g_tmph + ((size_t)b * SEQ + nbase + t) * KK + c0;
            *(uint2*)(outp) = hw;
            *(uint2*)(outp + 256) = lw;
        }
    }
}

// ---------------- launch ----------------
extern "C" void kernel_launch(void* const* d_in, const int* in_sizes, int n_in,
                              void* d_out, int out_size) {
    const float* x      = (const float*)d_in[0];
    const float* sinp   = (const float*)d_in[1];
    const float* cosp   = (const float*)d_in[2];
    const float* W_qkvo = (const float*)d_in[3];
    const float* b_qkvo = (const float*)d_in[4];
    const float* W_lepe = (const float*)d_in[5];
    const float* b_lepe = (const float*)d_in[6];
    const float* W_proj = (const float*)d_in[7];
    const float* b_proj = (const float*)d_in[8];
    float* out = (float*)d_out;

    __half *xs_p, *ws_p, *tmph_p, *wp_p;
    float* qkvo_p;
    cudaGetSymbolAddress((void**)&qkvo_p, g_qkvo);
    cudaGetSymbolAddress((void**)&xs_p, g_xs);
    cudaGetSymbolAddress((void**)&ws_p, g_ws);
    cudaGetSymbolAddress((void**)&tmph_p, g_tmph);
    cudaGetSymbolAddress((void**)&wp_p, g_wp);

    cudaFuncSetAttribute(gemm_half, cudaFuncAttributeMaxDynamicSharedMemorySize, GEMM_SMEM);

    const int M = BB * SEQ;  // 32768

    // 0) fused splits + zeroing, one launch
    prep_kernel<<<(TTOT + 255) / 256, 256>>>(x, W_qkvo, W_proj);

    // 1) qkvo = x @ W_qkvo^T + b  (HMMA, K=512 split)
    {
        dim3 grid(QKVO / BN, M / BM);
        gemm_half<<<grid, 256, GEMM_SMEM>>>(xs_p, ws_p, b_qkvo, qkvo_p, QKVO);
    }
    // 2) state reduction
    {
        dim3 grid(BB * NH, SEQ / CHUNK);
        reduce_kernel<<<grid, 256>>>(sinp, cosp);
    }
    // 3) attention epilogue (coalesced, 4 tokens/thread)
    {
        dim3 grid(SEQ / ATOKS, BB);
        attn_kernel<<<grid, 256>>>(sinp, cosp, W_lepe, b_lepe);
    }
    // 4) out = tmp @ W_proj^T + b_proj  (HMMA)
    {
        dim3 grid(DIM / BN, M / BM);
        gemm_half<<<grid, 256, GEMM_SMEM>>>(tmph_p, wp_p, b_proj, out, DIM);
    }
}

// round 14
// speedup vs baseline: 1.9581x; 1.2400x over previous
#include <cuda_runtime.h>
#include <cuda_fp16.h>
#include <math.h>
#include <stdint.h>

#define BB 4
#define SEQ 8192
#define DIM 256
#define NH 8
#define HD 32
#define INTERNAL 256
#define QKVO 1024
#define KK 256                      // single fp16 K (no hi/lo split)
#define SCALE_F 0.17677669529663687f
#define S_CONST 0.00464534038f

// ---------------- scratch ----------------
__device__ __align__(16) float g_qkvo[(size_t)BB * SEQ * QKVO];      // 128 MB
__device__ __align__(16) __half g_xs[(size_t)BB * SEQ * KK];         // 16 MB
__device__ __align__(16) __half g_ws[(size_t)QKVO * KK];             // 512 KB
__device__ __align__(16) __half g_tmph[(size_t)BB * SEQ * KK];       // 16 MB
__device__ __align__(16) __half g_wp[(size_t)DIM * KK];              // 128 KB
__device__ float g_kv[BB * NH * HD * HD];
__device__ float g_km[BB * NH * HD];
__device__ float g_vm[BB * NH * HD];

__device__ __forceinline__ float elu1(float x) { return x > 0.f ? x + 1.f : __expf(x); }

__device__ __forceinline__ uint32_t smem_u32(const void* p) {
    return (uint32_t)__cvta_generic_to_shared(p);
}
__device__ __forceinline__ void cpa16(uint32_t dst, const void* src) {
    asm volatile("cp.async.cg.shared.global [%0], [%1], 16;" :: "r"(dst), "l"(src));
}
__device__ __forceinline__ void cpa_commit() {
    asm volatile("cp.async.commit_group;" ::: "memory");
}
template <int N> __device__ __forceinline__ void cpa_wait() {
    asm volatile("cp.async.wait_group %0;" :: "n"(N) : "memory");
}
#define LDSM4(r, a) \
    asm volatile("ldmatrix.sync.aligned.m8n8.x4.shared.b16 {%0,%1,%2,%3}, [%4];" \
                 : "=r"((r)[0]), "=r"((r)[1]), "=r"((r)[2]), "=r"((r)[3]) : "r"(a))
#define MMA16816(d, a, b0, b1) \
    asm volatile("mma.sync.aligned.m16n8k16.row.col.f32.f16.f16.f32 " \
                 "{%0,%1,%2,%3},{%4,%5,%6,%7},{%8,%9},{%0,%1,%2,%3};" \
                 : "+f"((d)[0]), "+f"((d)[1]), "+f"((d)[2]), "+f"((d)[3]) \
                 : "r"((a)[0]), "r"((a)[1]), "r"((a)[2]), "r"((a)[3]), "r"(b0), "r"(b1))

// ---------------- GEMM config: 128x128 CTA, warp tile 32x64, 2 CTAs/SM ----------------
#define BM 128
#define BN 128
#define BK 64
#define NCH (KK / BK)               // 4
#define NSTG 3
#define TILEA (BM * 128)            // 16384 B
#define TILEB (BN * 128)            // 16384 B
#define STGB (TILEA + TILEB)        // 32768 B
#define GEMM_SMEM (NSTG * STGB)     // 98304 B

__device__ __forceinline__ void stage_tiles(uint32_t sb, const __half* Ab,
                                            const __half* Bb, int tid,
                                            int chunk, int buf) {
    const uint32_t ab = sb + buf * STGB;
    const uint32_t bbse = ab + TILEA;
    const __half* Ap = Ab + chunk * BK;
    const __half* Bp = Bb + chunk * BK;
#pragma unroll
    for (int i = 0; i < 4; i++) {
        int line = tid + i * 256;            // 0..1023
        int row = line >> 3, j = line & 7;
        uint32_t sw = row * 128 + ((j ^ (row & 7)) << 4);
        cpa16(ab + sw, Ap + (size_t)row * KK + j * 8);
    }
#pragma unroll
    for (int i = 0; i < 4; i++) {
        int line = tid + i * 256;
        int row = line >> 3, j = line & 7;
        uint32_t sw = row * 128 + ((j ^ (row & 7)) << 4);
        cpa16(bbse + sw, Bp + (size_t)row * KK + j * 8);
    }
    cpa_commit();
}

// C[M,Nn] = A[M,256]h @ B[Nn,256]h^T + bias (fp32 accum)
__global__ __launch_bounds__(256, 2)
void gemm_half(const __half* __restrict__ A, const __half* __restrict__ Bm,
               const float* __restrict__ bias, float* __restrict__ C, int Nn) {
    extern __shared__ char smem[];
    const uint32_t sb = smem_u32(smem);
    const int tid = threadIdx.x;
    const int wid = tid >> 5;
    const int lane = tid & 31;
    const int bm = blockIdx.y * BM;
    const int bn = blockIdx.x * BN;
    const int wm0 = (wid & 3) * 32;          // 4 warps in M
    const int wn0 = (wid >> 2) * 64;         // 2 warps in N

    const __half* Ab = A + (size_t)bm * KK;
    const __half* Bb = Bm + (size_t)bn * KK;

    float acc[2][8][4];
#pragma unroll
    for (int i = 0; i < 2; i++)
#pragma unroll
        for (int j = 0; j < 8; j++)
#pragma unroll
            for (int k = 0; k < 4; k++) acc[i][j][k] = 0.f;

    const int lrA = (lane & 7) + ((lane >> 3) & 1) * 8;
    const int lcA = ((lane >> 4) & 1) * 16;
    const int lrB = ((lane >> 4) & 1) * 8 + (lane & 7);
    const int lcB = ((lane >> 3) & 1) * 16;

    stage_tiles(sb, Ab, Bb, tid, 0, 0);
    stage_tiles(sb, Ab, Bb, tid, 1, 1);

    for (int c = 0; c < NCH; c++) {
        if (c + 2 < NCH) cpa_wait<1>(); else cpa_wait<0>();
        __syncthreads();
        if (c + 2 < NCH) stage_tiles(sb, Ab, Bb, tid, c + 2, (c + 2) % NSTG);
        const uint32_t ab = sb + (c % NSTG) * STGB;
        const uint32_t bbse = ab + TILEA;
#pragma unroll
        for (int ks = 0; ks < 4; ks++) {
            uint32_t afr[2][4], bfr[4][4];
#pragma unroll
            for (int mi = 0; mi < 2; mi++) {
                int r = wm0 + mi * 16 + lrA;
                uint32_t cc = (uint32_t)(ks * 32 + lcA);
                LDSM4(afr[mi], ab + r * 128 + (cc ^ ((r & 7) << 4)));
            }
#pragma unroll
            for (int bi = 0; bi < 4; bi++) {
                int r = wn0 + bi * 16 + lrB;
                uint32_t cc = (uint32_t)(ks * 32 + lcB);
                LDSM4(bfr[bi], bbse + r * 128 + (cc ^ ((r & 7) << 4)));
            }
#pragma unroll
            for (int mi = 0; mi < 2; mi++)
#pragma unroll
                for (int nj = 0; nj < 8; nj++)
                    MMA16816(acc[mi][nj], afr[mi],
                             bfr[nj >> 1][(nj & 1) * 2], bfr[nj >> 1][(nj & 1) * 2 + 1]);
        }
    }

    const int g = lane >> 2, t4 = lane & 3;
#pragma unroll
    for (int mi = 0; mi < 2; mi++) {
#pragma unroll
        for (int nj = 0; nj < 8; nj++) {
            const int col = bn + wn0 + nj * 8 + t4 * 2;
            const float2 bv = *(const float2*)(bias + col);
            const int row0 = bm + wm0 + mi * 16 + g;
            float2 o0 = {acc[mi][nj][0] + bv.x, acc[mi][nj][1] + bv.y};
            float2 o1 = {acc[mi][nj][2] + bv.x, acc[mi][nj][3] + bv.y};
            *(float2*)(C + (size_t)row0 * Nn + col) = o0;
            *(float2*)(C + (size_t)(row0 + 8) * Nn + col) = o1;
        }
    }
}

// ---------------- fused prep: fp16 conversions + accumulator zeroing, one launch --------
#define TX (BB * SEQ * DIM)         // 8388608
#define TW (QKVO * DIM)             // 262144
#define TP (DIM * DIM)              // 65536
#define NKV (BB * NH * HD * HD)     // 32768
#define NKM (BB * NH * HD)          // 1024
#define TTOT (TX + TW + TP + NKV + 2 * NKM)

__global__ void prep_kernel(const float* __restrict__ x,
                            const float* __restrict__ W_qkvo,
                            const float* __restrict__ W_proj) {
    int i = blockIdx.x * 256 + threadIdx.x;
    if (i >= TTOT) return;
    if (i < TX) {
        g_xs[i] = __float2half_rn(x[i]);
    } else if (i < TX + TW) {
        int k = i - TX;
        g_ws[k] = __float2half_rn(W_qkvo[k]);
    } else if (i < TX + TW + TP) {
        int k = i - TX - TW;
        g_wp[k] = __float2half_rn(W_proj[k]);
    } else {
        int k = i - TX - TW - TP;
        if (k < NKV) g_kv[k] = 0.f;
        else if (k < NKV + NKM) g_km[k - NKV] = 0.f;
        else g_vm[k - NKV - NKM] = 0.f;
    }
}

// ---------------- per-(b,h) state reduction: double-buffered, 1 sync / 8 tokens ----------
#define CHUNK 512
#define NIT (CHUNK / 8)
__global__ __launch_bounds__(256)
void reduce_kernel(const float* __restrict__ sinp, const float* __restrict__ cosp) {
    const int bh = blockIdx.x;
    const int chunk = blockIdx.y;
    const int b = bh / NH, h = bh % NH;
    const int tid = threadIdx.x;
    const int j = tid >> 5;                  // token sub 0..7
    const int d = tid & 31;
    const int dbase = j * 4;
    __shared__ float s_ks[2][8][32];
    __shared__ float s_vs[2][8][32];
    float acc[4] = {0.f, 0.f, 0.f, 0.f};
    float ksum = 0.f, vsum = 0.f;
    const int n0 = chunk * CHUNK;
    const float sgn = (d & 1) ? 1.f : -1.f;
    const size_t kcol = INTERNAL + h * HD;
    const size_t vcol = 2 * INTERNAL + h * HD;

    {
        const int n = n0 + j;
        const size_t row = ((size_t)b * SEQ + n) * QKVO;
        const float kh  = elu1(g_qkvo[row + kcol + d]);
        const float khp = elu1(g_qkvo[row + kcol + (d ^ 1)]);
        const float vv  = g_qkvo[row + vcol + d];
        const float sn = sinp[n * HD + d];
        const float cs = cosp[n * HD + d];
        s_ks[0][j][d] = (kh * cs + sgn * khp * sn) * S_CONST;
        s_vs[0][j][d] = vv * S_CONST;
        ksum += kh;
        vsum += vv;
    }
    __syncthreads();

    for (int it = 0; it < NIT; it++) {
        const int bsel = it & 1;
        float nk = 0.f, nkp = 0.f, nv = 0.f, nsn = 0.f, ncs = 0.f;
        const bool more = (it + 1 < NIT);
        if (more) {
            const int n = n0 + (it + 1) * 8 + j;
            const size_t row = ((size_t)b * SEQ + n) * QKVO;
            nk  = g_qkvo[row + kcol + d];
            nkp = g_qkvo[row + kcol + (d ^ 1)];
            nv  = g_qkvo[row + vcol + d];
            nsn = sinp[n * HD + d];
            ncs = cosp[n * HD + d];
        }
#pragma unroll
        for (int jj = 0; jj < 8; jj++) {
            const float vv = s_vs[bsel][jj][d];
#pragma unroll
            for (int dd = 0; dd < 4; dd++)
                acc[dd] += s_ks[bsel][jj][dbase + dd] * vv;
        }
        if (more) {
            const float kh = elu1(nk);
            const float khp = elu1(nkp);
            s_ks[bsel ^ 1][j][d] = (kh * ncs + sgn * khp * nsn) * S_CONST;
            s_vs[bsel ^ 1][j][d] = nv * S_CONST;
            ksum += kh;
            vsum += nv;
        }
        __syncthreads();
    }
#pragma unroll
    for (int dd = 0; dd < 4; dd++)
        atomicAdd(&g_kv[(bh * HD + dbase + dd) * HD + d], acc[dd]);
    atomicAdd(&g_km[bh * HD + d], ksum);
    atomicAdd(&g_vm[bh * HD + d], vsum);
}

// ---------------- attn epilogue: coalesced + 4 tokens/thread, hi-only output ----------
#define ATOKS 64
#define NPASS (ATOKS / 16)
__global__ __launch_bounds__(256, 3)
void attn_kernel(const float* __restrict__ sinp, const float* __restrict__ cosp,
                 const float* __restrict__ W_lepe, const float* __restrict__ b_lepe) {
    const int b = blockIdx.y;
    const int n0 = blockIdx.x * ATOKS;
    const int tid = threadIdx.x;
    const int tg = tid >> 6;                 // token group 0..3
    const int cq = tid & 63;                 // channel quad 0..63
    const int h = cq >> 3;
    const int eq = cq & 7;
    const int c0 = cq * 4;
    const int d0 = eq * 4;

    __shared__ __align__(16) float s_kv[NH][HD][36];   // 36864 B
    __shared__ __align__(16) float s_qs[16][NH * 36];  // 18432 B
    __shared__ float s_km[INTERNAL], s_vm[INTERNAL];
    __shared__ float s_w0[INTERNAL], s_w1[INTERNAL], s_w2[INTERNAL], s_bl[INTERNAL];

    for (int i = tid; i < NH * HD * HD; i += 256) {
        const int hh = i >> 10, rem = i & 1023;
        s_kv[hh][rem >> 5][rem & 31] = g_kv[b * NH * HD * HD + i];
    }
    {
        const int c = tid;
        const int bh = b * NH + (c >> 5);
        const int d = c & 31;
        const float invN = 1.f / (float)SEQ;
        s_km[c] = g_km[bh * HD + d] * invN;
        s_vm[c] = g_vm[bh * HD + d] * invN;
        s_w0[c] = W_lepe[c * 3 + 0];
        s_w1[c] = W_lepe[c * 3 + 1];
        s_w2[c] = W_lepe[c * 3 + 2];
        s_bl[c] = b_lepe[c];
    }
    __syncthreads();

    const unsigned FM = 0xffffffffu;
    const float km0 = s_km[c0], km1 = s_km[c0 + 1], km2 = s_km[c0 + 2], km3 = s_km[c0 + 3];
    const float vm0 = s_vm[c0], vm1 = s_vm[c0 + 1], vm2 = s_vm[c0 + 2], vm3 = s_vm[c0 + 3];
    const float w00 = s_w0[c0], w01 = s_w0[c0 + 1], w02 = s_w0[c0 + 2], w03 = s_w0[c0 + 3];
    const float w10 = s_w1[c0], w11 = s_w1[c0 + 1], w12 = s_w1[c0 + 2], w13 = s_w1[c0 + 3];
    const float w20 = s_w2[c0], w21 = s_w2[c0 + 1], w22 = s_w2[c0 + 2], w23 = s_w2[c0 + 3];
    const float bl0 = s_bl[c0], bl1 = s_bl[c0 + 1], bl2 = s_bl[c0 + 2], bl3 = s_bl[c0 + 3];

    for (int p = 0; p < NPASS; p++) {
        const int nbase = n0 + p * 16 + tg * 4;         // this thread's 4 tokens
        const size_t row0 = ((size_t)b * SEQ + nbase) * QKVO;
        float z[4];

        if (p) __syncthreads();              // prior pass matvec done reading s_qs
        // phase A: elu, z, theta-shift, write qs
#pragma unroll
        for (int t = 0; t < 4; t++) {
            const int n = nbase + t;
            const size_t row = row0 + (size_t)t * QKVO;
            const float4 qv = *(const float4*)(g_qkvo + row + c0);
            const float qh0 = elu1(qv.x), qh1 = elu1(qv.y);
            const float qh2 = elu1(qv.z), qh3 = elu1(qv.w);
            float zp = qh0 * km0 + qh1 * km1 + qh2 * km2 + qh3 * km3;
            zp += __shfl_xor_sync(FM, zp, 1);
            zp += __shfl_xor_sync(FM, zp, 2);
            zp += __shfl_xor_sync(FM, zp, 4);
            z[t] = zp * SCALE_F;
            const float4 sn4 = *(const float4*)(sinp + (size_t)n * HD + d0);
            const float4 cs4 = *(const float4*)(cosp + (size_t)n * HD + d0);
            float4 qs;
            qs.x = qh0 * cs4.x - qh1 * sn4.x;
            qs.y = qh1 * cs4.y + qh0 * sn4.y;
            qs.z = qh2 * cs4.z - qh3 * sn4.z;
            qs.w = qh3 * cs4.w + qh2 * sn4.w;
            *(float4*)(&s_qs[tg * 4 + t][h * 36 + d0]) = qs;
        }
        __syncthreads();

        // phase B: matvec, kv quads amortized over 4 tokens
        float a[4][4];
#pragma unroll
        for (int t = 0; t < 4; t++)
#pragma unroll
            for (int e = 0; e < 4; e++) a[t][e] = 0.f;
#pragma unroll
        for (int u = 0; u < 8; u++) {
            const float4 k0 = *(const float4*)(&s_kv[h][u * 4 + 0][d0]);
            const float4 k1 = *(const float4*)(&s_kv[h][u * 4 + 1][d0]);
            const float4 k2 = *(const float4*)(&s_kv[h][u * 4 + 2][d0]);
            const float4 k3 = *(const float4*)(&s_kv[h][u * 4 + 3][d0]);
#pragma unroll
            for (int t = 0; t < 4; t++) {
                const float4 q4 = *(const float4*)(&s_qs[tg * 4 + t][h * 36 + u * 4]);
                a[t][0] += q4.x * k0.x + q4.y * k1.x + q4.z * k2.x + q4.w * k3.x;
                a[t][1] += q4.x * k0.y + q4.y * k1.y + q4.z * k2.y + q4.w * k3.y;
                a[t][2] += q4.x * k0.z + q4.y * k1.z + q4.z * k2.z + q4.w * k3.z;
                a[t][3] += q4.x * k0.w + q4.y * k1.w + q4.z * k2.w + q4.w * k3.w;
            }
        }

        // phase C: epilogue, v-stencil chained in registers, hi-only store
        float4 v[4];
#pragma unroll
        for (int t = 0; t < 4; t++)
            v[t] = *(const float4*)(g_qkvo + row0 + (size_t)t * QKVO + 2 * INTERNAL + c0);
        const float4 vprev = (nbase > 0)
            ? *(const float4*)(g_qkvo + row0 - QKVO + 2 * INTERNAL + c0) : make_float4(0, 0, 0, 0);
        const float4 vnext = (nbase + 4 < SEQ)
            ? *(const float4*)(g_qkvo + row0 + 4 * QKVO + 2 * INTERNAL + c0) : make_float4(0, 0, 0, 0);

#pragma unroll
        for (int t = 0; t < 4; t++) {
            const size_t row = row0 + (size_t)t * QKVO;
            const float4 vp = (t == 0) ? vprev : v[t - 1];
            const float4 vn = (t == 3) ? vnext : v[t + 1];
            const float4 og = *(const float4*)(g_qkvo + row + 3 * INTERNAL + c0);
            const float zt = z[t];
            const float zf = 1.f + 1.f / (zt + 1e-6f);
            const float r0 = (a[t][0] * zf - zt * vm0
                        + vp.x * w00 + v[t].x * w10 + vn.x * w20 + bl0) * og.x;
            const float r1 = (a[t][1] * zf - zt * vm1
                        + vp.y * w01 + v[t].y * w11 + vn.y * w21 + bl1) * og.y;
            const float r2 = (a[t][2] * zf - zt * vm2
                        + vp.z * w02 + v[t].z * w12 + vn.z * w22 + bl2) * og.z;
            const float r3 = (a[t][3] * zf - zt * vm3
                        + vp.w * w03 + v[t].w * w13 + vn.w * w23 + bl3) * og.w;
            const __half h0 = __float2half_rn(r0), h1 = __float2half_rn(r1);
            const __half h2 = __float2half_rn(r2), h3 = __float2half_rn(r3);
            uint2 hw;
            hw.x = ((uint32_t)__half_as_ushort(h1) << 16) | __half_as_ushort(h0);
            hw.y = ((uint32_t)__half_as_ushort(h3) << 16) | __half_as_ushort(h2);
            __half* outp = g_tmph + ((size_t)b * SEQ + nbase + t) * KK + c0;
            *(uint2*)(outp) = hw;
        }
    }
}

// ---------------- launch ----------------
extern "C" void kernel_launch(void* const* d_in, const int* in_sizes, int n_in,
                              void* d_out, int out_size) {
    const float* x      = (const float*)d_in[0];
    const float* sinp   = (const float*)d_in[1];
    const float* cosp   = (const float*)d_in[2];
    const float* W_qkvo = (const float*)d_in[3];
    const float* b_qkvo = (const float*)d_in[4];
    const float* W_lepe = (const float*)d_in[5];
    const float* b_lepe = (const float*)d_in[6];
    const float* W_proj = (const float*)d_in[7];
    const float* b_proj = (const float*)d_in[8];
    float* out = (float*)d_out;

    __half *xs_p, *ws_p, *tmph_p, *wp_p;
    float* qkvo_p;
    cudaGetSymbolAddress((void**)&qkvo_p, g_qkvo);
    cudaGetSymbolAddress((void**)&xs_p, g_xs);
    cudaGetSymbolAddress((void**)&ws_p, g_ws);
    cudaGetSymbolAddress((void**)&tmph_p, g_tmph);
    cudaGetSymbolAddress((void**)&wp_p, g_wp);

    cudaFuncSetAttribute(gemm_half, cudaFuncAttributeMaxDynamicSharedMemorySize, GEMM_SMEM);

    const int M = BB * SEQ;  // 32768

    // 0) fused fp16 conversions + zeroing, one launch
    prep_kernel<<<(TTOT + 255) / 256, 256>>>(x, W_qkvo, W_proj);

    // 1) qkvo = x @ W_qkvo^T + b  (HMMA, K=256)
    {
        dim3 grid(QKVO / BN, M / BM);
        gemm_half<<<grid, 256, GEMM_SMEM>>>(xs_p, ws_p, b_qkvo, qkvo_p, QKVO);
    }
    // 2) state reduction
    {
        dim3 grid(BB * NH, SEQ / CHUNK);
        reduce_kernel<<<grid, 256>>>(sinp, cosp);
    }
    // 3) attention epilogue (coalesced, 4 tokens/thread)
    {
        dim3 grid(SEQ / ATOKS, BB);
        attn_kernel<<<grid, 256>>>(sinp, cosp, W_lepe, b_lepe);
    }
    // 4) out = tmp @ W_proj^T + b_proj  (HMMA, K=256)
    {
        dim3 grid(DIM / BN, M / BM);
        gemm_half<<<grid, 256, GEMM_SMEM>>>(tmph_p, wp_p, b_proj, out, DIM);
    }
}